// round 9
// baseline (speedup 1.0000x reference)
#include <cuda_runtime.h>
#include <cuda_bf16.h>
#include <math.h>
#include <stddef.h>

#define NN 50000
#define EE 800000
#define FF 64
#define EDD 16
#define GG 64
#define LL 2
#define SCB ((NN + 1023) / 1024)   // 49 scan blocks

typedef unsigned long long u64;
typedef unsigned int u32;

// ---------------- packed f32x2 helpers (sm_103a FFMA2 path) ----------------
__device__ __forceinline__ u64 pk2(float x, float y) {
    u64 r; asm("mov.b64 %0,{%1,%2};" : "=l"(r) : "f"(x), "f"(y)); return r;
}
__device__ __forceinline__ float2 up2(u64 v) {
    float2 r; asm("mov.b64 {%0,%1},%2;" : "=f"(r.x), "=f"(r.y) : "l"(v)); return r;
}
__device__ __forceinline__ u64 ffma2(u64 a, u64 b, u64 c) {
    u64 d; asm("fma.rn.f32x2 %0,%1,%2,%3;" : "=l"(d) : "l"(a), "l"(b), "l"(c)); return d;
}
__device__ __forceinline__ u64 fadd2(u64 a, u64 b) {
    u64 d; asm("add.rn.f32x2 %0,%1,%2;" : "=l"(d) : "l"(a), "l"(b)); return d;
}

// ---------------- bf16 helpers ----------------
__device__ __forceinline__ void mma16816(float* d, const u32* a, const u32* b) {
    asm volatile("mma.sync.aligned.m16n8k16.row.col.f32.bf16.bf16.f32 "
                 "{%0,%1,%2,%3},{%4,%5,%6,%7},{%8,%9},{%0,%1,%2,%3};"
                 : "+f"(d[0]), "+f"(d[1]), "+f"(d[2]), "+f"(d[3])
                 : "r"(a[0]), "r"(a[1]), "r"(a[2]), "r"(a[3]), "r"(b[0]), "r"(b[1]));
}
// split (a,b) into hi/lo bf16 pairs packed as u32
__device__ __forceinline__ void bfsplit2(float a, float b, u32& hi, u32& lo) {
    __nv_bfloat16 ah = __float2bfloat16_rn(a);
    __nv_bfloat16 bh = __float2bfloat16_rn(b);
    __nv_bfloat16 al = __float2bfloat16_rn(a - __bfloat162float(ah));
    __nv_bfloat16 bl = __float2bfloat16_rn(b - __bfloat162float(bh));
    unsigned short ahs = *reinterpret_cast<unsigned short*>(&ah);
    unsigned short bhs = *reinterpret_cast<unsigned short*>(&bh);
    unsigned short als = *reinterpret_cast<unsigned short*>(&al);
    unsigned short bls = *reinterpret_cast<unsigned short*>(&bl);
    hi = (u32)ahs | ((u32)bhs << 16);
    lo = (u32)als | ((u32)bls << 16);
}

// ---------------- scratch ----------------
__device__ int   g_deg[NN];
__device__ int   g_rowptr[NN + 1];
__device__ int   g_cursor[NN];
__device__ int   g_bsum[64];
__device__ int2  g_csr[EE];
__device__ float g_amp[NN];
__device__ float g_att[NN];
__device__ float g_logsum;
__device__ float g_P[NN * FF];
__device__ float g_Q[NN * FF];
__device__ float g_Wc[EDD * FF];
__device__ float g_hb[FF];
__device__ float g_Bp[320 * 192];
__device__ float g_C[(size_t)NN * 192];
__device__ float g_y[NN * FF];
__device__ float g_x[NN * FF];
__device__ float g_bnsum[FF];
__device__ float g_bnsq[FF];
__device__ float g_bnA[FF];
__device__ float g_bnB[FF];
__device__ float g_gsum[GG * FF];
__device__ int   g_gcnt[GG];
__device__ u64   g_ea2[(size_t)EE * EDD];     // duplicated edge_attr pairs {v,v}
// bf16 split operands for tensor-core GEMM
__device__ __nv_bfloat16 g_Ah[(size_t)NN * 320];
__device__ __nv_bfloat16 g_Al[(size_t)NN * 320];
__device__ __nv_bfloat16 g_Bth[192 * 320];    // transposed: [c][k]
__device__ __nv_bfloat16 g_Btl[192 * 320];

// ---------------- init / degree / CSR ----------------
__global__ void k_init() {
    int i  = blockIdx.x * blockDim.x + threadIdx.x;
    int nt = gridDim.x * blockDim.x;
    for (int j = i; j < NN; j += nt) { g_deg[j] = 0; g_cursor[j] = 0; }
    for (int j = i; j < GG * FF; j += nt) g_gsum[j] = 0.f;
    if (i < GG) g_gcnt[i] = 0;
    if (i == 0) g_logsum = 0.f;
}

__global__ void k_deg(const int* __restrict__ ei) {
    int e = blockIdx.x * blockDim.x + threadIdx.x;
    if (e < EE) atomicAdd(&g_deg[ei[EE + e]], 1);
}

__global__ void k_scan1() {
    int tid = threadIdx.x, lane = tid & 31, wid = tid >> 5;
    int i = blockIdx.x * 1024 + tid;
    int v = (i < NN) ? g_deg[i] : 0;
    float lv = (i < NN) ? logf((float)v + 1.0f) : 0.0f;
#pragma unroll
    for (int off = 16; off > 0; off >>= 1) lv += __shfl_xor_sync(0xffffffffu, lv, off);
    if (lane == 0) atomicAdd(&g_logsum, lv);
    int x = v;
#pragma unroll
    for (int off = 1; off < 32; off <<= 1) {
        int t = __shfl_up_sync(0xffffffffu, x, off);
        if (lane >= off) x += t;
    }
    __shared__ int ws[32];
    if (lane == 31) ws[wid] = x;
    __syncthreads();
    if (wid == 0) {
        int s = ws[lane];
#pragma unroll
        for (int off = 1; off < 32; off <<= 1) {
            int t = __shfl_up_sync(0xffffffffu, s, off);
            if (lane >= off) s += t;
        }
        ws[lane] = s;
    }
    __syncthreads();
    int wbase = wid ? ws[wid - 1] : 0;
    if (i < NN) g_rowptr[i] = wbase + x - v;
    if (tid == 1023) g_bsum[blockIdx.x] = wbase + x;
}

__global__ void k_scan3() {
    __shared__ int sb[64];
    __shared__ int s_off, s_tot;
    int t = threadIdx.x;
    if (t < 64) sb[t] = (t < SCB) ? g_bsum[t] : 0;
    __syncthreads();
    if (t == 0) {
        int off = 0, tot = 0;
        for (int j = 0; j < SCB; j++) {
            if (j < (int)blockIdx.x) off += sb[j];
            tot += sb[j];
        }
        s_off = off; s_tot = tot;
    }
    __syncthreads();
    int i = blockIdx.x * 1024 + t;
    if (i < NN) {
        g_rowptr[i] += s_off;
        float avg = g_logsum / (float)NN;
        float d = (float)g_deg[i];
        float logd = logf(fmaxf(d, 1.0f) + 1.0f);
        g_amp[i] = logd / avg;
        g_att[i] = avg / logd;
    }
    if (blockIdx.x == gridDim.x - 1 && t == 0) g_rowptr[NN] = s_tot;
}

__global__ void k_scatter(const int* __restrict__ ei) {
    int e = blockIdx.x * blockDim.x + threadIdx.x;
    if (e >= EE) return;
    int d = ei[EE + e];
    int pos = g_rowptr[d] + atomicAdd(&g_cursor[d], 1);
    g_csr[pos] = make_int2(ei[e], e);
}

// ---- duplicate edge_attr into {v,v} u64 pairs (once, reused both layers) ----
__global__ void k_dupea(const float* __restrict__ eattr) {
    int gid = blockIdx.x * blockDim.x + threadIdx.x;
    if (gid >= EE * 4) return;
    float4 v = *reinterpret_cast<const float4*>(&eattr[(size_t)gid * 4]);
    u64* dst = &g_ea2[(size_t)gid * 4];
    dst[0] = pk2(v.x, v.x);
    dst[1] = pk2(v.y, v.y);
    dst[2] = pk2(v.z, v.z);
    dst[3] = pk2(v.w, v.w);
}

// ---------------- per-layer small prep ----------------
__global__ void k_prep(const float* __restrict__ We_l, const float* __restrict__ be_l,
                       const float* __restrict__ Wpre_l, const float* __restrict__ bpre_l) {
    int tid = threadIdx.x;
    if (tid < FF) { g_bnsum[tid] = 0.f; g_bnsq[tid] = 0.f; }
    for (int idx = tid; idx < EDD * FF; idx += 256) {
        int j = idx / FF, f = idx % FF;
        float s = 0.f;
        for (int m = 0; m < FF; m++)
            s += We_l[j * FF + m] * Wpre_l[(128 + m) * FF + f];
        g_Wc[idx] = s;
    }
    if (tid < FF) {
        float s = bpre_l[tid];
        for (int m = 0; m < FF; m++)
            s += be_l[m] * Wpre_l[(128 + m) * FF + tid];
        g_hb[tid] = s;
    }
}

__global__ void k_pack(const float* __restrict__ Wpost_l) {
    int idx = blockIdx.x * blockDim.x + threadIdx.x;
    if (idx >= 320 * 192) return;
    int r = idx / 192, c = idx % 192;
    float v;
    if (r < 64) {
        v = (c < 64) ? Wpost_l[r * 64 + c] : 0.f;
    } else {
        int k = r - 64;
        int blk = c >> 6, cc = c & 63;
        v = Wpost_l[(64 + blk * 256 + k) * 64 + cc];
    }
    g_Bp[idx] = v;
}

// ---- B split + transpose: Bth/Btl[c][k] from Bp[k][c] ----
__global__ void k_cvtB() {
    int idx = blockIdx.x * blockDim.x + threadIdx.x;
    if (idx >= 320 * 192) return;
    int k = idx / 192, c = idx % 192;
    float v = g_Bp[idx];
    __nv_bfloat16 h = __float2bfloat16_rn(v);
    __nv_bfloat16 l = __float2bfloat16_rn(v - __bfloat162float(h));
    g_Bth[c * 320 + k] = h;
    g_Btl[c * 320 + k] = l;
}

// ---- x -> A cols 0..63 (layer 0 only; layer 1 fused into bnapply) ----
__global__ void k_cvtX(const float* __restrict__ X) {
    int gid = blockIdx.x * blockDim.x + threadIdx.x;
    if (gid >= NN * 16) return;
    int r = gid >> 4, q = gid & 15;
    float4 v = *reinterpret_cast<const float4*>(&X[(size_t)r * 64 + q * 4]);
    u32 h0, l0, h1, l1;
    bfsplit2(v.x, v.y, h0, l0);
    bfsplit2(v.z, v.w, h1, l1);
    *reinterpret_cast<u64*>(&g_Ah[(size_t)r * 320 + q * 4]) = (u64)h0 | ((u64)h1 << 32);
    *reinterpret_cast<u64*>(&g_Al[(size_t)r * 320 + q * 4]) = (u64)l0 | ((u64)l1 << 32);
}

// ---------------- P = x@Wa, Q = x@Wb (FFMA2) ----------------
__global__ void __launch_bounds__(256) k_pq(const float* __restrict__ xin,
                                            const float* __restrict__ Wpre_l) {
    const float* X = xin ? xin : g_x;
    __shared__ float xs_t[64][68];
    int tid = threadIdx.x;
    int n0 = blockIdx.x * 64;
#pragma unroll
    for (int it = 0; it < 4; it++) {
        int idx = tid + it * 256;
        int nl = idx >> 4, kq = idx & 15;
        int n = n0 + nl;
        float4 v = make_float4(0.f, 0.f, 0.f, 0.f);
        if (n < NN) v = *reinterpret_cast<const float4*>(&X[(size_t)n * FF + kq * 4]);
        xs_t[kq * 4 + 0][nl] = v.x;
        xs_t[kq * 4 + 1][nl] = v.y;
        xs_t[kq * 4 + 2][nl] = v.z;
        xs_t[kq * 4 + 3][nl] = v.w;
    }
    __syncthreads();
    int f = tid & 63, g = tid >> 6;
    u64 accP2[8], accQ2[8];
#pragma unroll
    for (int p = 0; p < 8; p++) { accP2[p] = 0ull; accQ2[p] = 0ull; }
#pragma unroll 2
    for (int k = 0; k < 64; k++) {
        float av = __ldg(&Wpre_l[k * 64 + f]);
        float bv = __ldg(&Wpre_l[4096 + k * 64 + f]);
        u64 a2 = pk2(av, av), b2 = pk2(bv, bv);
        ulonglong2 x01 = *reinterpret_cast<const ulonglong2*>(&xs_t[k][g * 16]);
        ulonglong2 x23 = *reinterpret_cast<const ulonglong2*>(&xs_t[k][g * 16 + 4]);
        ulonglong2 x45 = *reinterpret_cast<const ulonglong2*>(&xs_t[k][g * 16 + 8]);
        ulonglong2 x67 = *reinterpret_cast<const ulonglong2*>(&xs_t[k][g * 16 + 12]);
        u64 xv[8] = {x01.x, x01.y, x23.x, x23.y, x45.x, x45.y, x67.x, x67.y};
#pragma unroll
        for (int p = 0; p < 8; p++) {
            accP2[p] = ffma2(xv[p], a2, accP2[p]);
            accQ2[p] = ffma2(xv[p], b2, accQ2[p]);
        }
    }
#pragma unroll
    for (int p = 0; p < 8; p++) {
        int n = n0 + g * 16 + 2 * p;
        float2 vp = up2(accP2[p]), vq = up2(accQ2[p]);
        if (n < NN)     { g_P[(size_t)n * FF + f] = vp.x;       g_Q[(size_t)n * FF + f] = vq.x; }
        if (n + 1 < NN) { g_P[(size_t)(n + 1) * FF + f] = vp.y; g_Q[(size_t)(n + 1) * FF + f] = vq.y; }
    }
}

// ---------------- per-node aggregation (warp/node, dup-ea, bf16 epilogue) ----------------
__global__ void __launch_bounds__(128) k_agg() {
    int warp = (blockIdx.x * blockDim.x + threadIdx.x) >> 5;
    int lane = threadIdx.x & 31;
    if (warp >= NN) return;
    int n = warp;
    int fp = 2 * lane;
    u64 wc2[16];
#pragma unroll
    for (int k = 0; k < 16; k++) wc2[k] = *reinterpret_cast<const u64*>(&g_Wc[k * 64 + fp]);
    u64 base2 = fadd2(*reinterpret_cast<const u64*>(&g_P[(size_t)n * FF + fp]),
                      *reinterpret_cast<const u64*>(&g_hb[fp]));
    int s = g_rowptr[n], e = g_rowptr[n + 1];
    u64 sum2 = 0ull, sq2 = 0ull;
    float mn0 = 3.4e38f, mn1 = 3.4e38f, mx0 = -3.4e38f, mx1 = -3.4e38f;
    int2 se_n; u64 q_n = 0ull;
    if (s < e) {
        se_n = g_csr[s];
        q_n = *reinterpret_cast<const u64*>(&g_Q[(size_t)se_n.x * FF + fp]);
    }
    for (int i = s; i < e; i++) {
        int2 se = se_n;
        u64 qv = q_n;
        if (i + 1 < e) {
            se_n = g_csr[i + 1];
            q_n = *reinterpret_cast<const u64*>(&g_Q[(size_t)se_n.x * FF + fp]);
        }
        const u64* ep = &g_ea2[(size_t)se.y * EDD];
        u64 eav[16];
#pragma unroll
        for (int k = 0; k < 16; k += 2) {
            ulonglong2 v = *reinterpret_cast<const ulonglong2*>(ep + k);
            eav[k] = v.x; eav[k + 1] = v.y;
        }
        u64 hA = fadd2(base2, qv);
        u64 p0 = 0ull, p1 = 0ull;
#pragma unroll
        for (int k = 0; k < 8; k++) {
            p0 = ffma2(eav[2 * k], wc2[2 * k], p0);
            p1 = ffma2(eav[2 * k + 1], wc2[2 * k + 1], p1);
        }
        u64 h2 = fadd2(hA, fadd2(p0, p1));
        sum2 = fadd2(sum2, h2);
        sq2 = ffma2(h2, h2, sq2);
        float2 h = up2(h2);
        mn0 = fminf(mn0, h.x); mx0 = fmaxf(mx0, h.x);
        mn1 = fminf(mn1, h.y); mx1 = fmaxf(mx1, h.y);
    }
    float deg = (float)(e - s);
    float degc = fmaxf(deg, 1.0f);
    float2 sum = up2(sum2), sq = up2(sq2);
    float mean0 = sum.x / degc, mean1 = sum.y / degc;
    float std0 = sqrtf(fmaxf(sq.x / degc - mean0 * mean0, 0.f) + 1e-5f);
    float std1 = sqrtf(fmaxf(sq.y / degc - mean1 * mean1, 0.f) + 1e-5f);
    if (deg == 0.f) { mn0 = 0.f; mx0 = 0.f; mn1 = 0.f; mx1 = 0.f; }
    // write bf16 hi/lo splits directly into A cols 64..319
    __nv_bfloat16* ah = &g_Ah[(size_t)n * 320 + 64 + fp];
    __nv_bfloat16* al = &g_Al[(size_t)n * 320 + 64 + fp];
    u32 hi, lo;
    bfsplit2(mean0, mean1, hi, lo);
    *reinterpret_cast<u32*>(ah + 0)   = hi; *reinterpret_cast<u32*>(al + 0)   = lo;
    bfsplit2(mn0, mn1, hi, lo);
    *reinterpret_cast<u32*>(ah + 64)  = hi; *reinterpret_cast<u32*>(al + 64)  = lo;
    bfsplit2(mx0, mx1, hi, lo);
    *reinterpret_cast<u32*>(ah + 128) = hi; *reinterpret_cast<u32*>(al + 128) = lo;
    bfsplit2(std0, std1, hi, lo);
    *reinterpret_cast<u32*>(ah + 192) = hi; *reinterpret_cast<u32*>(al + 192) = lo;
}

// ---------------- tensor-core GEMM: C[N,192] = A @ B, bf16 3-term split ----------------
#define PITCH 40
__global__ void __launch_bounds__(256) k_gemm_tc() {
    __shared__ __nv_bfloat16 sAh[128 * PITCH];
    __shared__ __nv_bfloat16 sAl[128 * PITCH];
    __shared__ __nv_bfloat16 sBh[96 * PITCH];
    __shared__ __nv_bfloat16 sBl[96 * PITCH];
    int tid = threadIdx.x;
    int warp = tid >> 5, lane = tid & 31;
    int g = lane >> 2, t = lane & 3;
    int wm = warp >> 1, wn = warp & 1;
    int m0 = wm * 32;
    int nloc0 = wn * 48;
    int row0 = blockIdx.x * 128;
    int c0 = blockIdx.y * 96;
    float acc[2][6][4];
#pragma unroll
    for (int mi = 0; mi < 2; mi++)
#pragma unroll
        for (int j = 0; j < 6; j++)
#pragma unroll
            for (int q = 0; q < 4; q++) acc[mi][j][q] = 0.f;

    for (int kc = 0; kc < 320; kc += 32) {
#pragma unroll
        for (int it = 0; it < 4; it++) {
            int idx = tid + it * 256;
            int r = idx >> 3, kq = idx & 7;
            int n = row0 + r;
            u64 vh = 0ull, vl = 0ull;
            if (n < NN) {
                vh = *reinterpret_cast<const u64*>(&g_Ah[(size_t)n * 320 + kc + kq * 4]);
                vl = *reinterpret_cast<const u64*>(&g_Al[(size_t)n * 320 + kc + kq * 4]);
            }
            *reinterpret_cast<u64*>(&sAh[r * PITCH + kq * 4]) = vh;
            *reinterpret_cast<u64*>(&sAl[r * PITCH + kq * 4]) = vl;
        }
#pragma unroll
        for (int it = 0; it < 3; it++) {
            int idx = tid + it * 256;
            int r = idx >> 3, kq = idx & 7;
            *reinterpret_cast<u64*>(&sBh[r * PITCH + kq * 4]) =
                *reinterpret_cast<const u64*>(&g_Bth[(size_t)(c0 + r) * 320 + kc + kq * 4]);
            *reinterpret_cast<u64*>(&sBl[r * PITCH + kq * 4]) =
                *reinterpret_cast<const u64*>(&g_Btl[(size_t)(c0 + r) * 320 + kc + kq * 4]);
        }
        __syncthreads();
#pragma unroll
        for (int kk = 0; kk < 32; kk += 16) {
            u32 ah[2][4], al[2][4];
#pragma unroll
            for (int mi = 0; mi < 2; mi++) {
                int r = m0 + mi * 16 + g;
                int cA = kk + 2 * t;
                ah[mi][0] = *reinterpret_cast<const u32*>(&sAh[r * PITCH + cA]);
                ah[mi][1] = *reinterpret_cast<const u32*>(&sAh[(r + 8) * PITCH + cA]);
                ah[mi][2] = *reinterpret_cast<const u32*>(&sAh[r * PITCH + cA + 8]);
                ah[mi][3] = *reinterpret_cast<const u32*>(&sAh[(r + 8) * PITCH + cA + 8]);
                al[mi][0] = *reinterpret_cast<const u32*>(&sAl[r * PITCH + cA]);
                al[mi][1] = *reinterpret_cast<const u32*>(&sAl[(r + 8) * PITCH + cA]);
                al[mi][2] = *reinterpret_cast<const u32*>(&sAl[r * PITCH + cA + 8]);
                al[mi][3] = *reinterpret_cast<const u32*>(&sAl[(r + 8) * PITCH + cA + 8]);
            }
#pragma unroll
            for (int j = 0; j < 6; j++) {
                int nr = nloc0 + 8 * j + g;
                int cB = kk + 2 * t;
                u32 bh[2], bl[2];
                bh[0] = *reinterpret_cast<const u32*>(&sBh[nr * PITCH + cB]);
                bh[1] = *reinterpret_cast<const u32*>(&sBh[nr * PITCH + cB + 8]);
                bl[0] = *reinterpret_cast<const u32*>(&sBl[nr * PITCH + cB]);
                bl[1] = *reinterpret_cast<const u32*>(&sBl[nr * PITCH + cB + 8]);
#pragma unroll
                for (int mi = 0; mi < 2; mi++) {
                    mma16816(acc[mi][j], ah[mi], bh);
                    mma16816(acc[mi][j], ah[mi], bl);
                    mma16816(acc[mi][j], al[mi], bh);
                }
            }
        }
        __syncthreads();
    }
#pragma unroll
    for (int mi = 0; mi < 2; mi++) {
#pragma unroll
        for (int j = 0; j < 6; j++) {
            int r = row0 + m0 + mi * 16 + g;
            int c = c0 + nloc0 + 8 * j + 2 * t;
            if (r < NN)
                *reinterpret_cast<float2*>(&g_C[(size_t)r * 192 + c]) =
                    make_float2(acc[mi][j][0], acc[mi][j][1]);
            if (r + 8 < NN)
                *reinterpret_cast<float2*>(&g_C[(size_t)(r + 8) * 192 + c]) =
                    make_float2(acc[mi][j][2], acc[mi][j][3]);
        }
    }
}

// ---------------- combine + Wlin + BN stats ----------------
__global__ void __launch_bounds__(256) k_post(const float* __restrict__ Wlin_l,
                                              const float* __restrict__ bpost_l,
                                              const float* __restrict__ blin_l) {
    int f = threadIdx.x & 63;
    int g = threadIdx.x >> 6;
    u64 wl2[32];
#pragma unroll
    for (int p = 0; p < 32; p++)
        wl2[p] = pk2(Wlin_l[(2 * p) * 64 + f], Wlin_l[(2 * p + 1) * 64 + f]);
    __shared__ float sh[4][66];
    __shared__ float sred[256];
    float bp = bpost_l[f];
    float bl = blin_l[f];
    float ys = 0.f, yq = 0.f;
    int n0 = blockIdx.x * 32;
    for (int it = 0; it < 8; it++) {
        int n = n0 + it * 4 + g;
        bool valid = (n < NN);
        float o = 0.f;
        if (valid) {
            const float* c = &g_C[(size_t)n * 192];
            o = c[f] + g_amp[n] * c[64 + f] + g_att[n] * c[128 + f] + bp;
        }
        sh[g][f] = o;
        __syncthreads();
        if (valid) {
            u64 acc = 0ull;
#pragma unroll
            for (int p = 0; p < 32; p++)
                acc = ffma2(*reinterpret_cast<const u64*>(&sh[g][2 * p]), wl2[p], acc);
            float2 r = up2(acc);
            float y = r.x + r.y + bl;
            g_y[(size_t)n * FF + f] = y;
            ys += y;
            yq = fmaf(y, y, yq);
        }
        __syncthreads();
    }
    sred[threadIdx.x] = ys;
    __syncthreads();
    if (threadIdx.x < 64) {
        float s = sred[f] + sred[64 + f] + sred[128 + f] + sred[192 + f];
        atomicAdd(&g_bnsum[f], s);
    }
    __syncthreads();
    sred[threadIdx.x] = yq;
    __syncthreads();
    if (threadIdx.x < 64) {
        float s = sred[f] + sred[64 + f] + sred[128 + f] + sred[192 + f];
        atomicAdd(&g_bnsq[f], s);
    }
}

__global__ void k_bnfin(const float* __restrict__ gamma_l, const float* __restrict__ beta_l) {
    int f = threadIdx.x;
    if (f >= FF) return;
    float mu = g_bnsum[f] / (float)NN;
    float var = g_bnsq[f] / (float)NN - mu * mu;
    float rs = rsqrtf(var + 1e-5f);
    float a = rs * gamma_l[f];
    g_bnA[f] = a;
    g_bnB[f] = beta_l[f] - mu * a;
}

// layer-0: BN + ReLU -> g_x (for next pq) AND A cols 0..63 (bf16 split, for next gemm)
__global__ void k_bnapply() {
    int gid = blockIdx.x * blockDim.x + threadIdx.x;
    if (gid >= NN * 16) return;
    int r = gid >> 4, q = gid & 15;
    int f0 = q * 4;
    float4 y = *reinterpret_cast<const float4*>(&g_y[(size_t)r * 64 + f0]);
    float v0 = fmaxf(y.x * g_bnA[f0 + 0] + g_bnB[f0 + 0], 0.f);
    float v1 = fmaxf(y.y * g_bnA[f0 + 1] + g_bnB[f0 + 1], 0.f);
    float v2 = fmaxf(y.z * g_bnA[f0 + 2] + g_bnB[f0 + 2], 0.f);
    float v3 = fmaxf(y.w * g_bnA[f0 + 3] + g_bnB[f0 + 3], 0.f);
    *reinterpret_cast<float4*>(&g_x[(size_t)r * 64 + f0]) = make_float4(v0, v1, v2, v3);
    u32 h0, l0, h1, l1;
    bfsplit2(v0, v1, h0, l0);
    bfsplit2(v2, v3, h1, l1);
    *reinterpret_cast<u64*>(&g_Ah[(size_t)r * 320 + f0]) = (u64)h0 | ((u64)h1 << 32);
    *reinterpret_cast<u64*>(&g_Al[(size_t)r * 320 + f0]) = (u64)l0 | ((u64)l1 << 32);
}

// layer-1: BN + ReLU + mean-pool accumulate
__global__ void k_bnpool(const int* __restrict__ batch) {
    int gid = blockIdx.x * blockDim.x + threadIdx.x;
    if (gid >= NN * FF) return;
    int n = gid >> 6, f = gid & 63;
    float v = fmaxf(g_y[gid] * g_bnA[f] + g_bnB[f], 0.f);
    int b = batch[n];
    atomicAdd(&g_gsum[b * FF + f], v);
    if (f == 0) atomicAdd(&g_gcnt[b], 1);
}

__global__ void k_head(const float* __restrict__ W1, const float* __restrict__ b1,
                       const float* __restrict__ W2, const float* __restrict__ b2,
                       float* __restrict__ out) {
    int g = threadIdx.x;
    if (g >= GG) return;
    float cnt = fmaxf((float)g_gcnt[g], 1.0f);
    float inv = 1.0f / cnt;
    float gm[64];
#pragma unroll
    for (int k = 0; k < 64; k++) gm[k] = g_gsum[g * FF + k] * inv;
    float o = b2[0];
    for (int j = 0; j < 40; j++) {
        float s = b1[j];
#pragma unroll
        for (int k = 0; k < 64; k++) s = fmaf(gm[k], W1[k * 40 + j], s);
        o = fmaf(fmaxf(s, 0.f), W2[j], o);
    }
    out[g] = o;
}

// ---------------- launch ----------------
extern "C" void kernel_launch(void* const* d_in, const int* in_sizes, int n_in,
                              void* d_out, int out_size) {
    const float* x     = (const float*)d_in[0];
    const float* ea    = (const float*)d_in[1];
    const float* We    = (const float*)d_in[2];
    const float* be    = (const float*)d_in[3];
    const float* Wpre  = (const float*)d_in[4];
    const float* bpre  = (const float*)d_in[5];
    const float* Wpost = (const float*)d_in[6];
    const float* bpost = (const float*)d_in[7];
    const float* Wlin  = (const float*)d_in[8];
    const float* blin  = (const float*)d_in[9];
    const float* gamma = (const float*)d_in[10];
    const float* beta  = (const float*)d_in[11];
    const float* W1    = (const float*)d_in[12];
    const float* b1    = (const float*)d_in[13];
    const float* W2    = (const float*)d_in[14];
    const float* b2    = (const float*)d_in[15];
    const int*   ei    = (const int*)d_in[16];
    const int*   batch = (const int*)d_in[17];
    float* out = (float*)d_out;

    k_init<<<256, 256>>>();                         // idx 0
    k_deg<<<(EE + 255) / 256, 256>>>(ei);           // idx 1
    k_scan1<<<SCB, 1024>>>();                       // idx 2
    k_pq<<<(NN + 63) / 64, 256>>>(x, Wpre);         // idx 3  <- PROFILED LAUNCH
    k_scan3<<<SCB, 1024>>>();                       // idx 4
    k_scatter<<<(EE + 255) / 256, 256>>>(ei);       // idx 5
    k_dupea<<<(EE * 4 + 255) / 256, 256>>>(ea);     // idx 6
    k_cvtX<<<(NN * 16 + 255) / 256, 256>>>(x);      // idx 7

    for (int l = 0; l < LL; l++) {
        k_prep<<<1, 256>>>(We + l * EDD * FF, be + l * FF, Wpre + l * 192 * FF, bpre + l * FF);
        k_pack<<<(320 * 192 + 255) / 256, 256>>>(Wpost + l * 832 * FF);
        k_cvtB<<<(320 * 192 + 255) / 256, 256>>>();
        if (l > 0) k_pq<<<(NN + 63) / 64, 256>>>(nullptr, Wpre + l * 192 * FF);
        k_agg<<<(NN + 3) / 4, 128>>>();
        dim3 gg((NN + 127) / 128, 2);
        k_gemm_tc<<<gg, 256>>>();
        k_post<<<(NN + 31) / 32, 256>>>(Wlin + l * FF * FF, bpost + l * FF, blin + l * FF);
        k_bnfin<<<1, 64>>>(gamma + l * FF, beta + l * FF);
        if (l == 0) k_bnapply<<<(NN * 16 + 255) / 256, 256>>>();
        else        k_bnpool<<<(NN * FF + 255) / 256, 256>>>(batch);
    }

    k_head<<<1, 64>>>(W1, b1, W2, b2, out);
}

// round 10
// speedup vs baseline: 1.3131x; 1.3131x over previous
#include <cuda_runtime.h>
#include <cuda_bf16.h>
#include <math.h>
#include <stddef.h>

#define NN 50000
#define EE 800000
#define FF 64
#define EDD 16
#define GG 64
#define LL 2
#define SCB ((NN + 1023) / 1024)   // 49 scan blocks

typedef unsigned long long u64;
typedef unsigned int u32;

// ---------------- packed f32x2 helpers (sm_103a FFMA2 path) ----------------
__device__ __forceinline__ u64 pk2(float x, float y) {
    u64 r; asm("mov.b64 %0,{%1,%2};" : "=l"(r) : "f"(x), "f"(y)); return r;
}
__device__ __forceinline__ float2 up2(u64 v) {
    float2 r; asm("mov.b64 {%0,%1},%2;" : "=f"(r.x), "=f"(r.y) : "l"(v)); return r;
}
__device__ __forceinline__ u64 ffma2(u64 a, u64 b, u64 c) {
    u64 d; asm("fma.rn.f32x2 %0,%1,%2,%3;" : "=l"(d) : "l"(a), "l"(b), "l"(c)); return d;
}
__device__ __forceinline__ u64 fadd2(u64 a, u64 b) {
    u64 d; asm("add.rn.f32x2 %0,%1,%2;" : "=l"(d) : "l"(a), "l"(b)); return d;
}

// ---------------- bf16 helpers ----------------
__device__ __forceinline__ void mma16816(float* d, const u32* a, const u32* b) {
    asm volatile("mma.sync.aligned.m16n8k16.row.col.f32.bf16.bf16.f32 "
                 "{%0,%1,%2,%3},{%4,%5,%6,%7},{%8,%9},{%0,%1,%2,%3};"
                 : "+f"(d[0]), "+f"(d[1]), "+f"(d[2]), "+f"(d[3])
                 : "r"(a[0]), "r"(a[1]), "r"(a[2]), "r"(a[3]), "r"(b[0]), "r"(b[1]));
}
// split (a,b) into hi/lo bf16 pairs packed as u32
__device__ __forceinline__ void bfsplit2(float a, float b, u32& hi, u32& lo) {
    __nv_bfloat16 ah = __float2bfloat16_rn(a);
    __nv_bfloat16 bh = __float2bfloat16_rn(b);
    __nv_bfloat16 al = __float2bfloat16_rn(a - __bfloat162float(ah));
    __nv_bfloat16 bl = __float2bfloat16_rn(b - __bfloat162float(bh));
    unsigned short ahs = *reinterpret_cast<unsigned short*>(&ah);
    unsigned short bhs = *reinterpret_cast<unsigned short*>(&bh);
    unsigned short als = *reinterpret_cast<unsigned short*>(&al);
    unsigned short bls = *reinterpret_cast<unsigned short*>(&bl);
    hi = (u32)ahs | ((u32)bhs << 16);
    lo = (u32)als | ((u32)bls << 16);
}

// ---------------- scratch ----------------
__device__ int   g_deg[NN];
__device__ int   g_rowptr[NN + 1];
__device__ int   g_cursor[NN];
__device__ int   g_bsum[64];
__device__ int   g_csr_src[EE];
__device__ float g_eaperm[(size_t)EE * EDD];  // edge_attr permuted into CSR order
__device__ float g_amp[NN];
__device__ float g_att[NN];
__device__ float g_logsum;
__device__ float g_P[NN * FF];
__device__ float g_Q[NN * FF];
__device__ float g_Wc[EDD * FF];
__device__ float g_hb[FF];
__device__ float g_Bp[320 * 192];
__device__ float g_C[(size_t)NN * 192];
__device__ float g_y[NN * FF];
__device__ float g_x[NN * FF];
__device__ float g_bnsum[FF];
__device__ float g_bnsq[FF];
__device__ float g_bnA[FF];
__device__ float g_bnB[FF];
__device__ float g_gsum[GG * FF];
__device__ int   g_gcnt[GG];
// bf16 split operands for tensor-core GEMM
__device__ __nv_bfloat16 g_Ah[(size_t)NN * 320];
__device__ __nv_bfloat16 g_Al[(size_t)NN * 320];
__device__ __nv_bfloat16 g_Bth[192 * 320];    // transposed: [c][k]
__device__ __nv_bfloat16 g_Btl[192 * 320];

// ---------------- init / degree / CSR ----------------
__global__ void k_init() {
    int i  = blockIdx.x * blockDim.x + threadIdx.x;
    int nt = gridDim.x * blockDim.x;
    for (int j = i; j < NN; j += nt) { g_deg[j] = 0; g_cursor[j] = 0; }
    for (int j = i; j < GG * FF; j += nt) g_gsum[j] = 0.f;
    if (i < GG) g_gcnt[i] = 0;
    if (i == 0) g_logsum = 0.f;
}

__global__ void k_deg(const int* __restrict__ ei) {
    int e = blockIdx.x * blockDim.x + threadIdx.x;
    if (e < EE) atomicAdd(&g_deg[ei[EE + e]], 1);
}

__global__ void k_scan1() {
    int tid = threadIdx.x, lane = tid & 31, wid = tid >> 5;
    int i = blockIdx.x * 1024 + tid;
    int v = (i < NN) ? g_deg[i] : 0;
    float lv = (i < NN) ? logf((float)v + 1.0f) : 0.0f;
#pragma unroll
    for (int off = 16; off > 0; off >>= 1) lv += __shfl_xor_sync(0xffffffffu, lv, off);
    if (lane == 0) atomicAdd(&g_logsum, lv);
    int x = v;
#pragma unroll
    for (int off = 1; off < 32; off <<= 1) {
        int t = __shfl_up_sync(0xffffffffu, x, off);
        if (lane >= off) x += t;
    }
    __shared__ int ws[32];
    if (lane == 31) ws[wid] = x;
    __syncthreads();
    if (wid == 0) {
        int s = ws[lane];
#pragma unroll
        for (int off = 1; off < 32; off <<= 1) {
            int t = __shfl_up_sync(0xffffffffu, s, off);
            if (lane >= off) s += t;
        }
        ws[lane] = s;
    }
    __syncthreads();
    int wbase = wid ? ws[wid - 1] : 0;
    if (i < NN) g_rowptr[i] = wbase + x - v;
    if (tid == 1023) g_bsum[blockIdx.x] = wbase + x;
}

__global__ void k_scan3() {
    __shared__ int sb[64];
    __shared__ int s_off, s_tot;
    int t = threadIdx.x;
    if (t < 64) sb[t] = (t < SCB) ? g_bsum[t] : 0;
    __syncthreads();
    if (t == 0) {
        int off = 0, tot = 0;
        for (int j = 0; j < SCB; j++) {
            if (j < (int)blockIdx.x) off += sb[j];
            tot += sb[j];
        }
        s_off = off; s_tot = tot;
    }
    __syncthreads();
    int i = blockIdx.x * 1024 + t;
    if (i < NN) {
        g_rowptr[i] += s_off;
        float avg = g_logsum / (float)NN;
        float d = (float)g_deg[i];
        float logd = logf(fmaxf(d, 1.0f) + 1.0f);
        g_amp[i] = logd / avg;
        g_att[i] = avg / logd;
    }
    if (blockIdx.x == gridDim.x - 1 && t == 0) g_rowptr[NN] = s_tot;
}

// scatter: build CSR src list AND permute edge_attr rows into CSR slot order
__global__ void k_scatter(const int* __restrict__ ei, const float* __restrict__ eattr) {
    int e = blockIdx.x * blockDim.x + threadIdx.x;
    if (e >= EE) return;
    int d = ei[EE + e];
    int pos = g_rowptr[d] + atomicAdd(&g_cursor[d], 1);
    g_csr_src[pos] = ei[e];
    const float4* srcp = reinterpret_cast<const float4*>(&eattr[(size_t)e * EDD]);
    float4* dstp = reinterpret_cast<float4*>(&g_eaperm[(size_t)pos * EDD]);
    dstp[0] = srcp[0];
    dstp[1] = srcp[1];
    dstp[2] = srcp[2];
    dstp[3] = srcp[3];
}

// ---------------- per-layer small prep ----------------
__global__ void k_prep(const float* __restrict__ We_l, const float* __restrict__ be_l,
                       const float* __restrict__ Wpre_l, const float* __restrict__ bpre_l) {
    int tid = threadIdx.x;
    if (tid < FF) { g_bnsum[tid] = 0.f; g_bnsq[tid] = 0.f; }
    for (int idx = tid; idx < EDD * FF; idx += 256) {
        int j = idx / FF, f = idx % FF;
        float s = 0.f;
        for (int m = 0; m < FF; m++)
            s += We_l[j * FF + m] * Wpre_l[(128 + m) * FF + f];
        g_Wc[idx] = s;
    }
    if (tid < FF) {
        float s = bpre_l[tid];
        for (int m = 0; m < FF; m++)
            s += be_l[m] * Wpre_l[(128 + m) * FF + tid];
        g_hb[tid] = s;
    }
}

__global__ void k_pack(const float* __restrict__ Wpost_l) {
    int idx = blockIdx.x * blockDim.x + threadIdx.x;
    if (idx >= 320 * 192) return;
    int r = idx / 192, c = idx % 192;
    float v;
    if (r < 64) {
        v = (c < 64) ? Wpost_l[r * 64 + c] : 0.f;
    } else {
        int k = r - 64;
        int blk = c >> 6, cc = c & 63;
        v = Wpost_l[(64 + blk * 256 + k) * 64 + cc];
    }
    g_Bp[idx] = v;
}

// ---- B split + transpose: Bth/Btl[c][k] from Bp[k][c] ----
__global__ void k_cvtB() {
    int idx = blockIdx.x * blockDim.x + threadIdx.x;
    if (idx >= 320 * 192) return;
    int k = idx / 192, c = idx % 192;
    float v = g_Bp[idx];
    __nv_bfloat16 h = __float2bfloat16_rn(v);
    __nv_bfloat16 l = __float2bfloat16_rn(v - __bfloat162float(h));
    g_Bth[c * 320 + k] = h;
    g_Btl[c * 320 + k] = l;
}

// ---- x -> A cols 0..63 (layer 0 only; layer 1 fused into bnapply) ----
__global__ void k_cvtX(const float* __restrict__ X) {
    int gid = blockIdx.x * blockDim.x + threadIdx.x;
    if (gid >= NN * 16) return;
    int r = gid >> 4, q = gid & 15;
    float4 v = *reinterpret_cast<const float4*>(&X[(size_t)r * 64 + q * 4]);
    u32 h0, l0, h1, l1;
    bfsplit2(v.x, v.y, h0, l0);
    bfsplit2(v.z, v.w, h1, l1);
    *reinterpret_cast<u64*>(&g_Ah[(size_t)r * 320 + q * 4]) = (u64)h0 | ((u64)h1 << 32);
    *reinterpret_cast<u64*>(&g_Al[(size_t)r * 320 + q * 4]) = (u64)l0 | ((u64)l1 << 32);
}

// ---------------- P = x@Wa, Q = x@Wb (FFMA2) ----------------
__global__ void __launch_bounds__(256) k_pq(const float* __restrict__ xin,
                                            const float* __restrict__ Wpre_l) {
    const float* X = xin ? xin : g_x;
    __shared__ float xs_t[64][68];
    int tid = threadIdx.x;
    int n0 = blockIdx.x * 64;
#pragma unroll
    for (int it = 0; it < 4; it++) {
        int idx = tid + it * 256;
        int nl = idx >> 4, kq = idx & 15;
        int n = n0 + nl;
        float4 v = make_float4(0.f, 0.f, 0.f, 0.f);
        if (n < NN) v = *reinterpret_cast<const float4*>(&X[(size_t)n * FF + kq * 4]);
        xs_t[kq * 4 + 0][nl] = v.x;
        xs_t[kq * 4 + 1][nl] = v.y;
        xs_t[kq * 4 + 2][nl] = v.z;
        xs_t[kq * 4 + 3][nl] = v.w;
    }
    __syncthreads();
    int f = tid & 63, g = tid >> 6;
    u64 accP2[8], accQ2[8];
#pragma unroll
    for (int p = 0; p < 8; p++) { accP2[p] = 0ull; accQ2[p] = 0ull; }
#pragma unroll 2
    for (int k = 0; k < 64; k++) {
        float av = __ldg(&Wpre_l[k * 64 + f]);
        float bv = __ldg(&Wpre_l[4096 + k * 64 + f]);
        u64 a2 = pk2(av, av), b2 = pk2(bv, bv);
        ulonglong2 x01 = *reinterpret_cast<const ulonglong2*>(&xs_t[k][g * 16]);
        ulonglong2 x23 = *reinterpret_cast<const ulonglong2*>(&xs_t[k][g * 16 + 4]);
        ulonglong2 x45 = *reinterpret_cast<const ulonglong2*>(&xs_t[k][g * 16 + 8]);
        ulonglong2 x67 = *reinterpret_cast<const ulonglong2*>(&xs_t[k][g * 16 + 12]);
        u64 xv[8] = {x01.x, x01.y, x23.x, x23.y, x45.x, x45.y, x67.x, x67.y};
#pragma unroll
        for (int p = 0; p < 8; p++) {
            accP2[p] = ffma2(xv[p], a2, accP2[p]);
            accQ2[p] = ffma2(xv[p], b2, accQ2[p]);
        }
    }
#pragma unroll
    for (int p = 0; p < 8; p++) {
        int n = n0 + g * 16 + 2 * p;
        float2 vp = up2(accP2[p]), vq = up2(accQ2[p]);
        if (n < NN)     { g_P[(size_t)n * FF + f] = vp.x;       g_Q[(size_t)n * FF + f] = vq.x; }
        if (n + 1 < NN) { g_P[(size_t)(n + 1) * FF + f] = vp.y; g_Q[(size_t)(n + 1) * FF + f] = vq.y; }
    }
}

// ---------------- per-node aggregation (warp/node, sequential ea, bf16 epilogue) ----------------
__global__ void __launch_bounds__(256) k_agg() {
    int warp = (blockIdx.x * blockDim.x + threadIdx.x) >> 5;
    int lane = threadIdx.x & 31;
    if (warp >= NN) return;
    int n = warp;
    int fp = 2 * lane;
    u64 wc2[16];
#pragma unroll
    for (int k = 0; k < 16; k++) wc2[k] = *reinterpret_cast<const u64*>(&g_Wc[k * 64 + fp]);
    u64 base2 = fadd2(*reinterpret_cast<const u64*>(&g_P[(size_t)n * FF + fp]),
                      *reinterpret_cast<const u64*>(&g_hb[fp]));
    int s = g_rowptr[n], e = g_rowptr[n + 1];
    u64 sum2 = 0ull, sq2 = 0ull;
    float mn0 = 3.4e38f, mn1 = 3.4e38f, mx0 = -3.4e38f, mx1 = -3.4e38f;
    int src_n = 0; u64 q_n = 0ull;
    if (s < e) {
        src_n = g_csr_src[s];
        q_n = *reinterpret_cast<const u64*>(&g_Q[(size_t)src_n * FF + fp]);
    }
    for (int i = s; i < e; i++) {
        u64 qv = q_n;
        if (i + 1 < e) {
            src_n = g_csr_src[i + 1];
            q_n = *reinterpret_cast<const u64*>(&g_Q[(size_t)src_n * FF + fp]);
        }
        const float* ep = &g_eaperm[(size_t)i * EDD];   // sequential!
        float eav[16];
#pragma unroll
        for (int k = 0; k < 16; k += 4) {
            float4 v = *reinterpret_cast<const float4*>(ep + k);
            eav[k] = v.x; eav[k + 1] = v.y; eav[k + 2] = v.z; eav[k + 3] = v.w;
        }
        u64 hA = fadd2(base2, qv);
        u64 p0 = 0ull, p1 = 0ull;
#pragma unroll
        for (int k = 0; k < 8; k++) {
            p0 = ffma2(pk2(eav[2 * k], eav[2 * k]), wc2[2 * k], p0);
            p1 = ffma2(pk2(eav[2 * k + 1], eav[2 * k + 1]), wc2[2 * k + 1], p1);
        }
        u64 h2 = fadd2(hA, fadd2(p0, p1));
        sum2 = fadd2(sum2, h2);
        sq2 = ffma2(h2, h2, sq2);
        float2 h = up2(h2);
        mn0 = fminf(mn0, h.x); mx0 = fmaxf(mx0, h.x);
        mn1 = fminf(mn1, h.y); mx1 = fmaxf(mx1, h.y);
    }
    float deg = (float)(e - s);
    float degc = fmaxf(deg, 1.0f);
    float2 sum = up2(sum2), sq = up2(sq2);
    float mean0 = sum.x / degc, mean1 = sum.y / degc;
    float std0 = sqrtf(fmaxf(sq.x / degc - mean0 * mean0, 0.f) + 1e-5f);
    float std1 = sqrtf(fmaxf(sq.y / degc - mean1 * mean1, 0.f) + 1e-5f);
    if (deg == 0.f) { mn0 = 0.f; mx0 = 0.f; mn1 = 0.f; mx1 = 0.f; }
    // write bf16 hi/lo splits directly into A cols 64..319
    __nv_bfloat16* ah = &g_Ah[(size_t)n * 320 + 64 + fp];
    __nv_bfloat16* al = &g_Al[(size_t)n * 320 + 64 + fp];
    u32 hi, lo;
    bfsplit2(mean0, mean1, hi, lo);
    *reinterpret_cast<u32*>(ah + 0)   = hi; *reinterpret_cast<u32*>(al + 0)   = lo;
    bfsplit2(mn0, mn1, hi, lo);
    *reinterpret_cast<u32*>(ah + 64)  = hi; *reinterpret_cast<u32*>(al + 64)  = lo;
    bfsplit2(mx0, mx1, hi, lo);
    *reinterpret_cast<u32*>(ah + 128) = hi; *reinterpret_cast<u32*>(al + 128) = lo;
    bfsplit2(std0, std1, hi, lo);
    *reinterpret_cast<u32*>(ah + 192) = hi; *reinterpret_cast<u32*>(al + 192) = lo;
}

// ---------------- tensor-core GEMM: C[N,192] = A @ B, bf16 3-term split ----------------
#define PITCH 40
__global__ void __launch_bounds__(256) k_gemm_tc() {
    __shared__ __nv_bfloat16 sAh[128 * PITCH];
    __shared__ __nv_bfloat16 sAl[128 * PITCH];
    __shared__ __nv_bfloat16 sBh[96 * PITCH];
    __shared__ __nv_bfloat16 sBl[96 * PITCH];
    int tid = threadIdx.x;
    int warp = tid >> 5, lane = tid & 31;
    int g = lane >> 2, t = lane & 3;
    int wm = warp >> 1, wn = warp & 1;
    int m0 = wm * 32;
    int nloc0 = wn * 48;
    int row0 = blockIdx.x * 128;
    int c0 = blockIdx.y * 96;
    float acc[2][6][4];
#pragma unroll
    for (int mi = 0; mi < 2; mi++)
#pragma unroll
        for (int j = 0; j < 6; j++)
#pragma unroll
            for (int q = 0; q < 4; q++) acc[mi][j][q] = 0.f;

    for (int kc = 0; kc < 320; kc += 32) {
#pragma unroll
        for (int it = 0; it < 4; it++) {
            int idx = tid + it * 256;
            int r = idx >> 3, kq = idx & 7;
            int n = row0 + r;
            u64 vh = 0ull, vl = 0ull;
            if (n < NN) {
                vh = *reinterpret_cast<const u64*>(&g_Ah[(size_t)n * 320 + kc + kq * 4]);
                vl = *reinterpret_cast<const u64*>(&g_Al[(size_t)n * 320 + kc + kq * 4]);
            }
            *reinterpret_cast<u64*>(&sAh[r * PITCH + kq * 4]) = vh;
            *reinterpret_cast<u64*>(&sAl[r * PITCH + kq * 4]) = vl;
        }
#pragma unroll
        for (int it = 0; it < 3; it++) {
            int idx = tid + it * 256;
            int r = idx >> 3, kq = idx & 7;
            *reinterpret_cast<u64*>(&sBh[r * PITCH + kq * 4]) =
                *reinterpret_cast<const u64*>(&g_Bth[(size_t)(c0 + r) * 320 + kc + kq * 4]);
            *reinterpret_cast<u64*>(&sBl[r * PITCH + kq * 4]) =
                *reinterpret_cast<const u64*>(&g_Btl[(size_t)(c0 + r) * 320 + kc + kq * 4]);
        }
        __syncthreads();
#pragma unroll
        for (int kk = 0; kk < 32; kk += 16) {
            u32 ah[2][4], al[2][4];
#pragma unroll
            for (int mi = 0; mi < 2; mi++) {
                int r = m0 + mi * 16 + g;
                int cA = kk + 2 * t;
                ah[mi][0] = *reinterpret_cast<const u32*>(&sAh[r * PITCH + cA]);
                ah[mi][1] = *reinterpret_cast<const u32*>(&sAh[(r + 8) * PITCH + cA]);
                ah[mi][2] = *reinterpret_cast<const u32*>(&sAh[r * PITCH + cA + 8]);
                ah[mi][3] = *reinterpret_cast<const u32*>(&sAh[(r + 8) * PITCH + cA + 8]);
                al[mi][0] = *reinterpret_cast<const u32*>(&sAl[r * PITCH + cA]);
                al[mi][1] = *reinterpret_cast<const u32*>(&sAl[(r + 8) * PITCH + cA]);
                al[mi][2] = *reinterpret_cast<const u32*>(&sAl[r * PITCH + cA + 8]);
                al[mi][3] = *reinterpret_cast<const u32*>(&sAl[(r + 8) * PITCH + cA + 8]);
            }
#pragma unroll
            for (int j = 0; j < 6; j++) {
                int nr = nloc0 + 8 * j + g;
                int cB = kk + 2 * t;
                u32 bh[2], bl[2];
                bh[0] = *reinterpret_cast<const u32*>(&sBh[nr * PITCH + cB]);
                bh[1] = *reinterpret_cast<const u32*>(&sBh[nr * PITCH + cB + 8]);
                bl[0] = *reinterpret_cast<const u32*>(&sBl[nr * PITCH + cB]);
                bl[1] = *reinterpret_cast<const u32*>(&sBl[nr * PITCH + cB + 8]);
#pragma unroll
                for (int mi = 0; mi < 2; mi++) {
                    mma16816(acc[mi][j], ah[mi], bh);
                    mma16816(acc[mi][j], ah[mi], bl);
                    mma16816(acc[mi][j], al[mi], bh);
                }
            }
        }
        __syncthreads();
    }
#pragma unroll
    for (int mi = 0; mi < 2; mi++) {
#pragma unroll
        for (int j = 0; j < 6; j++) {
            int r = row0 + m0 + mi * 16 + g;
            int c = c0 + nloc0 + 8 * j + 2 * t;
            if (r < NN)
                *reinterpret_cast<float2*>(&g_C[(size_t)r * 192 + c]) =
                    make_float2(acc[mi][j][0], acc[mi][j][1]);
            if (r + 8 < NN)
                *reinterpret_cast<float2*>(&g_C[(size_t)(r + 8) * 192 + c]) =
                    make_float2(acc[mi][j][2], acc[mi][j][3]);
        }
    }
}

// ---------------- combine + Wlin + BN stats ----------------
__global__ void __launch_bounds__(256) k_post(const float* __restrict__ Wlin_l,
                                              const float* __restrict__ bpost_l,
                                              const float* __restrict__ blin_l) {
    int f = threadIdx.x & 63;
    int g = threadIdx.x >> 6;
    u64 wl2[32];
#pragma unroll
    for (int p = 0; p < 32; p++)
        wl2[p] = pk2(Wlin_l[(2 * p) * 64 + f], Wlin_l[(2 * p + 1) * 64 + f]);
    __shared__ float sh[4][66];
    __shared__ float sred[256];
    float bp = bpost_l[f];
    float bl = blin_l[f];
    float ys = 0.f, yq = 0.f;
    int n0 = blockIdx.x * 32;
    for (int it = 0; it < 8; it++) {
        int n = n0 + it * 4 + g;
        bool valid = (n < NN);
        float o = 0.f;
        if (valid) {
            const float* c = &g_C[(size_t)n * 192];
            o = c[f] + g_amp[n] * c[64 + f] + g_att[n] * c[128 + f] + bp;
        }
        sh[g][f] = o;
        __syncthreads();
        if (valid) {
            u64 acc = 0ull;
#pragma unroll
            for (int p = 0; p < 32; p++)
                acc = ffma2(*reinterpret_cast<const u64*>(&sh[g][2 * p]), wl2[p], acc);
            float2 r = up2(acc);
            float y = r.x + r.y + bl;
            g_y[(size_t)n * FF + f] = y;
            ys += y;
            yq = fmaf(y, y, yq);
        }
        __syncthreads();
    }
    sred[threadIdx.x] = ys;
    __syncthreads();
    if (threadIdx.x < 64) {
        float s = sred[f] + sred[64 + f] + sred[128 + f] + sred[192 + f];
        atomicAdd(&g_bnsum[f], s);
    }
    __syncthreads();
    sred[threadIdx.x] = yq;
    __syncthreads();
    if (threadIdx.x < 64) {
        float s = sred[f] + sred[64 + f] + sred[128 + f] + sred[192 + f];
        atomicAdd(&g_bnsq[f], s);
    }
}

__global__ void k_bnfin(const float* __restrict__ gamma_l, const float* __restrict__ beta_l) {
    int f = threadIdx.x;
    if (f >= FF) return;
    float mu = g_bnsum[f] / (float)NN;
    float var = g_bnsq[f] / (float)NN - mu * mu;
    float rs = rsqrtf(var + 1e-5f);
    float a = rs * gamma_l[f];
    g_bnA[f] = a;
    g_bnB[f] = beta_l[f] - mu * a;
}

// layer-0: BN + ReLU -> g_x (for next pq) AND A cols 0..63 (bf16 split, for next gemm)
__global__ void k_bnapply() {
    int gid = blockIdx.x * blockDim.x + threadIdx.x;
    if (gid >= NN * 16) return;
    int r = gid >> 4, q = gid & 15;
    int f0 = q * 4;
    float4 y = *reinterpret_cast<const float4*>(&g_y[(size_t)r * 64 + f0]);
    float v0 = fmaxf(y.x * g_bnA[f0 + 0] + g_bnB[f0 + 0], 0.f);
    float v1 = fmaxf(y.y * g_bnA[f0 + 1] + g_bnB[f0 + 1], 0.f);
    float v2 = fmaxf(y.z * g_bnA[f0 + 2] + g_bnB[f0 + 2], 0.f);
    float v3 = fmaxf(y.w * g_bnA[f0 + 3] + g_bnB[f0 + 3], 0.f);
    *reinterpret_cast<float4*>(&g_x[(size_t)r * 64 + f0]) = make_float4(v0, v1, v2, v3);
    u32 h0, l0, h1, l1;
    bfsplit2(v0, v1, h0, l0);
    bfsplit2(v2, v3, h1, l1);
    *reinterpret_cast<u64*>(&g_Ah[(size_t)r * 320 + f0]) = (u64)h0 | ((u64)h1 << 32);
    *reinterpret_cast<u64*>(&g_Al[(size_t)r * 320 + f0]) = (u64)l0 | ((u64)l1 << 32);
}

// layer-1: BN + ReLU + mean-pool accumulate
__global__ void k_bnpool(const int* __restrict__ batch) {
    int gid = blockIdx.x * blockDim.x + threadIdx.x;
    if (gid >= NN * FF) return;
    int n = gid >> 6, f = gid & 63;
    float v = fmaxf(g_y[gid] * g_bnA[f] + g_bnB[f], 0.f);
    int b = batch[n];
    atomicAdd(&g_gsum[b * FF + f], v);
    if (f == 0) atomicAdd(&g_gcnt[b], 1);
}

__global__ void k_head(const float* __restrict__ W1, const float* __restrict__ b1,
                       const float* __restrict__ W2, const float* __restrict__ b2,
                       float* __restrict__ out) {
    int g = threadIdx.x;
    if (g >= GG) return;
    float cnt = fmaxf((float)g_gcnt[g], 1.0f);
    float inv = 1.0f / cnt;
    float gm[64];
#pragma unroll
    for (int k = 0; k < 64; k++) gm[k] = g_gsum[g * FF + k] * inv;
    float o = b2[0];
    for (int j = 0; j < 40; j++) {
        float s = b1[j];
#pragma unroll
        for (int k = 0; k < 64; k++) s = fmaf(gm[k], W1[k * 40 + j], s);
        o = fmaf(fmaxf(s, 0.f), W2[j], o);
    }
    out[g] = o;
}

// ---------------- launch ----------------
extern "C" void kernel_launch(void* const* d_in, const int* in_sizes, int n_in,
                              void* d_out, int out_size) {
    const float* x     = (const float*)d_in[0];
    const float* ea    = (const float*)d_in[1];
    const float* We    = (const float*)d_in[2];
    const float* be    = (const float*)d_in[3];
    const float* Wpre  = (const float*)d_in[4];
    const float* bpre  = (const float*)d_in[5];
    const float* Wpost = (const float*)d_in[6];
    const float* bpost = (const float*)d_in[7];
    const float* Wlin  = (const float*)d_in[8];
    const float* blin  = (const float*)d_in[9];
    const float* gamma = (const float*)d_in[10];
    const float* beta  = (const float*)d_in[11];
    const float* W1    = (const float*)d_in[12];
    const float* b1    = (const float*)d_in[13];
    const float* W2    = (const float*)d_in[14];
    const float* b2    = (const float*)d_in[15];
    const int*   ei    = (const int*)d_in[16];
    const int*   batch = (const int*)d_in[17];
    float* out = (float*)d_out;

    k_init<<<256, 256>>>();                         // idx 0
    k_deg<<<(EE + 255) / 256, 256>>>(ei);           // idx 1
    k_scan1<<<SCB, 1024>>>();                       // idx 2
    k_pq<<<(NN + 63) / 64, 256>>>(x, Wpre);         // idx 3  <- PROFILED LAUNCH
    k_scan3<<<SCB, 1024>>>();                       // idx 4
    k_scatter<<<(EE + 255) / 256, 256>>>(ei, ea);   // idx 5 (CSR + ea permute)
    k_cvtX<<<(NN * 16 + 255) / 256, 256>>>(x);      // idx 6

    for (int l = 0; l < LL; l++) {
        k_prep<<<1, 256>>>(We + l * EDD * FF, be + l * FF, Wpre + l * 192 * FF, bpre + l * FF);
        k_pack<<<(320 * 192 + 255) / 256, 256>>>(Wpost + l * 832 * FF);
        k_cvtB<<<(320 * 192 + 255) / 256, 256>>>();
        if (l > 0) k_pq<<<(NN + 63) / 64, 256>>>(nullptr, Wpre + l * 192 * FF);
        k_agg<<<(NN + 7) / 8, 256>>>();
        dim3 gg((NN + 127) / 128, 2);
        k_gemm_tc<<<gg, 256>>>();
        k_post<<<(NN + 31) / 32, 256>>>(Wlin + l * FF * FF, bpost + l * FF, blin + l * FF);
        k_bnfin<<<1, 64>>>(gamma + l * FF, beta + l * FF);
        if (l == 0) k_bnapply<<<(NN * 16 + 255) / 256, 256>>>();
        else        k_bnpool<<<(NN * FF + 255) / 256, 256>>>(batch);
    }

    k_head<<<1, 64>>>(W1, b1, W2, b2, out);
}

// round 11
// speedup vs baseline: 1.4386x; 1.0955x over previous
#include <cuda_runtime.h>
#include <cuda_bf16.h>
#include <math.h>
#include <stddef.h>

#define NN 50000
#define EE 800000
#define FF 64
#define EDD 16
#define GG 64
#define LL 2
#define SCB ((NN + 1023) / 1024)   // 49 scan blocks

typedef unsigned long long u64;
typedef unsigned int u32;

// ---------------- packed f32x2 helpers ----------------
__device__ __forceinline__ u64 pk2(float x, float y) {
    u64 r; asm("mov.b64 %0,{%1,%2};" : "=l"(r) : "f"(x), "f"(y)); return r;
}
__device__ __forceinline__ float2 up2(u64 v) {
    float2 r; asm("mov.b64 {%0,%1},%2;" : "=f"(r.x), "=f"(r.y) : "l"(v)); return r;
}
__device__ __forceinline__ u64 ffma2(u64 a, u64 b, u64 c) {
    u64 d; asm("fma.rn.f32x2 %0,%1,%2,%3;" : "=l"(d) : "l"(a), "l"(b), "l"(c)); return d;
}
__device__ __forceinline__ u64 fadd2(u64 a, u64 b) {
    u64 d; asm("add.rn.f32x2 %0,%1,%2;" : "=l"(d) : "l"(a), "l"(b)); return d;
}

// ---------------- bf16 helpers ----------------
__device__ __forceinline__ void mma16816(float* d, const u32* a, const u32* b) {
    asm volatile("mma.sync.aligned.m16n8k16.row.col.f32.bf16.bf16.f32 "
                 "{%0,%1,%2,%3},{%4,%5,%6,%7},{%8,%9},{%0,%1,%2,%3};"
                 : "+f"(d[0]), "+f"(d[1]), "+f"(d[2]), "+f"(d[3])
                 : "r"(a[0]), "r"(a[1]), "r"(a[2]), "r"(a[3]), "r"(b[0]), "r"(b[1]));
}
__device__ __forceinline__ void bfsplit2(float a, float b, u32& hi, u32& lo) {
    __nv_bfloat16 ah = __float2bfloat16_rn(a);
    __nv_bfloat16 bh = __float2bfloat16_rn(b);
    __nv_bfloat16 al = __float2bfloat16_rn(a - __bfloat162float(ah));
    __nv_bfloat16 bl = __float2bfloat16_rn(b - __bfloat162float(bh));
    unsigned short ahs = *reinterpret_cast<unsigned short*>(&ah);
    unsigned short bhs = *reinterpret_cast<unsigned short*>(&bh);
    unsigned short als = *reinterpret_cast<unsigned short*>(&al);
    unsigned short bls = *reinterpret_cast<unsigned short*>(&bl);
    hi = (u32)ahs | ((u32)bhs << 16);
    lo = (u32)als | ((u32)bls << 16);
}

// ---------------- scratch ----------------
__device__ int   g_deg[NN];
__device__ int   g_rowptr[NN + 1];
__device__ int   g_cursor[NN];
__device__ int   g_bsum[64];
__device__ int   g_csr_src[EE];
__device__ float g_eaperm[(size_t)EE * EDD];  // edge_attr permuted into CSR order
__device__ float g_amp[NN];
__device__ float g_att[NN];
__device__ float g_logsum;
__device__ float g_P[NN * FF];
__device__ float g_Q[NN * FF];
__device__ float g_Wc[EDD * FF];
__device__ float g_hb[FF];
__device__ float g_Bp[320 * 192];
__device__ float g_Bp2[320 * 192];            // Bp @ Wlin (per 64-col block)
__device__ float g_bias2[FF];                 // bpost@Wlin + blin
__device__ float g_C[(size_t)NN * 192];
__device__ float g_y[NN * FF];
__device__ float g_bnsum[FF];
__device__ float g_bnsq[FF];
__device__ float g_bnA[FF];
__device__ float g_bnB[FF];
__device__ float g_gsum[GG * FF];
__device__ int   g_gcnt[GG];
// bf16 split operands for tensor-core GEMMs
__device__ __nv_bfloat16 g_Ah[(size_t)NN * 320];
__device__ __nv_bfloat16 g_Al[(size_t)NN * 320];
__device__ __nv_bfloat16 g_Bth[192 * 320];    // main B transposed: [c][k]
__device__ __nv_bfloat16 g_Btl[192 * 320];
__device__ __nv_bfloat16 g_Wth[128 * 64];     // PQ weights transposed: [c][k]
__device__ __nv_bfloat16 g_Wtl[128 * 64];

// ---------------- init / degree / CSR ----------------
__global__ void k_init() {
    int i  = blockIdx.x * blockDim.x + threadIdx.x;
    int nt = gridDim.x * blockDim.x;
    for (int j = i; j < NN; j += nt) { g_deg[j] = 0; g_cursor[j] = 0; }
    for (int j = i; j < GG * FF; j += nt) g_gsum[j] = 0.f;
    if (i < GG) g_gcnt[i] = 0;
    if (i == 0) g_logsum = 0.f;
}

__global__ void k_deg(const int* __restrict__ ei) {
    int e = blockIdx.x * blockDim.x + threadIdx.x;
    if (e < EE) atomicAdd(&g_deg[ei[EE + e]], 1);
}

__global__ void k_scan1() {
    int tid = threadIdx.x, lane = tid & 31, wid = tid >> 5;
    int i = blockIdx.x * 1024 + tid;
    int v = (i < NN) ? g_deg[i] : 0;
    float lv = (i < NN) ? logf((float)v + 1.0f) : 0.0f;
#pragma unroll
    for (int off = 16; off > 0; off >>= 1) lv += __shfl_xor_sync(0xffffffffu, lv, off);
    if (lane == 0) atomicAdd(&g_logsum, lv);
    int x = v;
#pragma unroll
    for (int off = 1; off < 32; off <<= 1) {
        int t = __shfl_up_sync(0xffffffffu, x, off);
        if (lane >= off) x += t;
    }
    __shared__ int ws[32];
    if (lane == 31) ws[wid] = x;
    __syncthreads();
    if (wid == 0) {
        int s = ws[lane];
#pragma unroll
        for (int off = 1; off < 32; off <<= 1) {
            int t = __shfl_up_sync(0xffffffffu, s, off);
            if (lane >= off) s += t;
        }
        ws[lane] = s;
    }
    __syncthreads();
    int wbase = wid ? ws[wid - 1] : 0;
    if (i < NN) g_rowptr[i] = wbase + x - v;
    if (tid == 1023) g_bsum[blockIdx.x] = wbase + x;
}

__global__ void k_scan3() {
    __shared__ int sb[64];
    __shared__ int s_off, s_tot;
    int t = threadIdx.x;
    if (t < 64) sb[t] = (t < SCB) ? g_bsum[t] : 0;
    __syncthreads();
    if (t == 0) {
        int off = 0, tot = 0;
        for (int j = 0; j < SCB; j++) {
            if (j < (int)blockIdx.x) off += sb[j];
            tot += sb[j];
        }
        s_off = off; s_tot = tot;
    }
    __syncthreads();
    int i = blockIdx.x * 1024 + t;
    if (i < NN) {
        g_rowptr[i] += s_off;
        float avg = g_logsum / (float)NN;
        float d = (float)g_deg[i];
        float logd = logf(fmaxf(d, 1.0f) + 1.0f);
        g_amp[i] = logd / avg;
        g_att[i] = avg / logd;
    }
    if (blockIdx.x == gridDim.x - 1 && t == 0) g_rowptr[NN] = s_tot;
}

// scatter: build CSR src list AND permute edge_attr rows into CSR slot order
__global__ void k_scatter(const int* __restrict__ ei, const float* __restrict__ eattr) {
    int e = blockIdx.x * blockDim.x + threadIdx.x;
    if (e >= EE) return;
    int d = ei[EE + e];
    int pos = g_rowptr[d] + atomicAdd(&g_cursor[d], 1);
    g_csr_src[pos] = ei[e];
    const float4* srcp = reinterpret_cast<const float4*>(&eattr[(size_t)e * EDD]);
    float4* dstp = reinterpret_cast<float4*>(&g_eaperm[(size_t)pos * EDD]);
    dstp[0] = srcp[0];
    dstp[1] = srcp[1];
    dstp[2] = srcp[2];
    dstp[3] = srcp[3];
}

// ---------------- per-layer small prep ----------------
__global__ void k_prep(const float* __restrict__ We_l, const float* __restrict__ be_l,
                       const float* __restrict__ Wpre_l, const float* __restrict__ bpre_l) {
    int tid = threadIdx.x;
    if (tid < FF) { g_bnsum[tid] = 0.f; g_bnsq[tid] = 0.f; }
    for (int idx = tid; idx < EDD * FF; idx += 256) {
        int j = idx / FF, f = idx % FF;
        float s = 0.f;
        for (int m = 0; m < FF; m++)
            s += We_l[j * FF + m] * Wpre_l[(128 + m) * FF + f];
        g_Wc[idx] = s;
    }
    if (tid < FF) {
        float s = bpre_l[tid];
        for (int m = 0; m < FF; m++)
            s += be_l[m] * Wpre_l[(128 + m) * FF + tid];
        g_hb[tid] = s;
    }
}

__global__ void k_pack(const float* __restrict__ Wpost_l) {
    int idx = blockIdx.x * blockDim.x + threadIdx.x;
    if (idx >= 320 * 192) return;
    int r = idx / 192, c = idx % 192;
    float v;
    if (r < 64) {
        v = (c < 64) ? Wpost_l[r * 64 + c] : 0.f;
    } else {
        int k = r - 64;
        int blk = c >> 6, cc = c & 63;
        v = Wpost_l[(64 + blk * 256 + k) * 64 + cc];
    }
    g_Bp[idx] = v;
}

// ---- fold Wlin: Bp2[r][blk*64+cc] = sum_m Bp[r][blk*64+m] * Wlin[m][cc] ----
__global__ void k_pack2(const float* __restrict__ Wlin_l) {
    int idx = blockIdx.x * blockDim.x + threadIdx.x;
    if (idx >= 320 * 192) return;
    int r = idx / 192, c = idx % 192;
    int blk = c >> 6, cc = c & 63;
    const float* bsrc = &g_Bp[r * 192 + blk * 64];
    float s = 0.f;
#pragma unroll 8
    for (int m = 0; m < 64; m++)
        s += bsrc[m] * __ldg(&Wlin_l[m * 64 + cc]);
    g_Bp2[idx] = s;
}

// ---- bias2 = bpost @ Wlin + blin ----
__global__ void k_bias2(const float* __restrict__ bpost_l, const float* __restrict__ blin_l,
                        const float* __restrict__ Wlin_l) {
    int cc = threadIdx.x;
    if (cc >= FF) return;
    float s = blin_l[cc];
    for (int m = 0; m < 64; m++)
        s += bpost_l[m] * Wlin_l[m * 64 + cc];
    g_bias2[cc] = s;
}

// ---- B split + transpose: Bth/Btl[c][k] from Bp2[k][c] ----
__global__ void k_cvtB() {
    int idx = blockIdx.x * blockDim.x + threadIdx.x;
    if (idx >= 320 * 192) return;
    int k = idx / 192, c = idx % 192;
    float v = g_Bp2[idx];
    __nv_bfloat16 h = __float2bfloat16_rn(v);
    __nv_bfloat16 l = __float2bfloat16_rn(v - __bfloat162float(h));
    g_Bth[c * 320 + k] = h;
    g_Btl[c * 320 + k] = l;
}

// ---- PQ weights split+transpose: Wth/Wtl[c][k], c<64 -> Wa col c, c>=64 -> Wb col c-64 ----
__global__ void k_cvtW(const float* __restrict__ Wpre_l) {
    int idx = blockIdx.x * blockDim.x + threadIdx.x;
    if (idx >= 128 * 64) return;
    int c = idx >> 6, k = idx & 63;
    float v = (c < 64) ? Wpre_l[k * 64 + c] : Wpre_l[(64 + k) * 64 + (c - 64)];
    __nv_bfloat16 h = __float2bfloat16_rn(v);
    __nv_bfloat16 l = __float2bfloat16_rn(v - __bfloat162float(h));
    g_Wth[c * 64 + k] = h;
    g_Wtl[c * 64 + k] = l;
}

// ---- x -> A cols 0..63 (layer 0; layer 1 via bnapply) ----
__global__ void k_cvtX(const float* __restrict__ X) {
    int gid = blockIdx.x * blockDim.x + threadIdx.x;
    if (gid >= NN * 16) return;
    int r = gid >> 4, q = gid & 15;
    float4 v = *reinterpret_cast<const float4*>(&X[(size_t)r * 64 + q * 4]);
    u32 h0, l0, h1, l1;
    bfsplit2(v.x, v.y, h0, l0);
    bfsplit2(v.z, v.w, h1, l1);
    *reinterpret_cast<u64*>(&g_Ah[(size_t)r * 320 + q * 4]) = (u64)h0 | ((u64)h1 << 32);
    *reinterpret_cast<u64*>(&g_Al[(size_t)r * 320 + q * 4]) = (u64)l0 | ((u64)l1 << 32);
}

// ---------------- TC GEMM: [P|Q][N,128] = X(bf16 split) @ Wt, k=64 ----------------
#define PITCH 40
__global__ void __launch_bounds__(256) k_pq_tc() {
    __shared__ __nv_bfloat16 sAh[128 * PITCH];
    __shared__ __nv_bfloat16 sAl[128 * PITCH];
    __shared__ __nv_bfloat16 sBh[128 * PITCH];
    __shared__ __nv_bfloat16 sBl[128 * PITCH];
    int tid = threadIdx.x;
    int warp = tid >> 5, lane = tid & 31;
    int g = lane >> 2, t = lane & 3;
    int wm = warp >> 1, wn = warp & 1;
    int m0 = wm * 32;
    int cb = wn * 64;
    int row0 = blockIdx.x * 128;
    float acc[2][8][4];
#pragma unroll
    for (int mi = 0; mi < 2; mi++)
#pragma unroll
        for (int j = 0; j < 8; j++)
#pragma unroll
            for (int q = 0; q < 4; q++) acc[mi][j][q] = 0.f;

#pragma unroll
    for (int kc = 0; kc < 64; kc += 32) {
        // A: 128 rows x 32 k -> 1024 u64, 4/thread (A cols 0..63, stride 320)
#pragma unroll
        for (int it = 0; it < 4; it++) {
            int idx = tid + it * 256;
            int r = idx >> 3, kq = idx & 7;
            int n = row0 + r;
            u64 vh = 0ull, vl = 0ull;
            if (n < NN) {
                vh = *reinterpret_cast<const u64*>(&g_Ah[(size_t)n * 320 + kc + kq * 4]);
                vl = *reinterpret_cast<const u64*>(&g_Al[(size_t)n * 320 + kc + kq * 4]);
            }
            *reinterpret_cast<u64*>(&sAh[r * PITCH + kq * 4]) = vh;
            *reinterpret_cast<u64*>(&sAl[r * PITCH + kq * 4]) = vl;
        }
        // B: 128 c-rows x 32 k -> 1024 u64, 4/thread
#pragma unroll
        for (int it = 0; it < 4; it++) {
            int idx = tid + it * 256;
            int r = idx >> 3, kq = idx & 7;
            *reinterpret_cast<u64*>(&sBh[r * PITCH + kq * 4]) =
                *reinterpret_cast<const u64*>(&g_Wth[r * 64 + kc + kq * 4]);
            *reinterpret_cast<u64*>(&sBl[r * PITCH + kq * 4]) =
                *reinterpret_cast<const u64*>(&g_Wtl[r * 64 + kc + kq * 4]);
        }
        __syncthreads();
#pragma unroll
        for (int kk = 0; kk < 32; kk += 16) {
            u32 ah[2][4], al[2][4];
#pragma unroll
            for (int mi = 0; mi < 2; mi++) {
                int r = m0 + mi * 16 + g;
                int cA = kk + 2 * t;
                ah[mi][0] = *reinterpret_cast<const u32*>(&sAh[r * PITCH + cA]);
                ah[mi][1] = *reinterpret_cast<const u32*>(&sAh[(r + 8) * PITCH + cA]);
                ah[mi][2] = *reinterpret_cast<const u32*>(&sAh[r * PITCH + cA + 8]);
                ah[mi][3] = *reinterpret_cast<const u32*>(&sAh[(r + 8) * PITCH + cA + 8]);
                al[mi][0] = *reinterpret_cast<const u32*>(&sAl[r * PITCH + cA]);
                al[mi][1] = *reinterpret_cast<const u32*>(&sAl[(r + 8) * PITCH + cA]);
                al[mi][2] = *reinterpret_cast<const u32*>(&sAl[r * PITCH + cA + 8]);
                al[mi][3] = *reinterpret_cast<const u32*>(&sAl[(r + 8) * PITCH + cA + 8]);
            }
#pragma unroll
            for (int j = 0; j < 8; j++) {
                int nr = cb + 8 * j + g;
                int cB = kk + 2 * t;
                u32 bh[2], bl[2];
                bh[0] = *reinterpret_cast<const u32*>(&sBh[nr * PITCH + cB]);
                bh[1] = *reinterpret_cast<const u32*>(&sBh[nr * PITCH + cB + 8]);
                bl[0] = *reinterpret_cast<const u32*>(&sBl[nr * PITCH + cB]);
                bl[1] = *reinterpret_cast<const u32*>(&sBl[nr * PITCH + cB + 8]);
#pragma unroll
                for (int mi = 0; mi < 2; mi++) {
                    mma16816(acc[mi][j], ah[mi], bh);
                    mma16816(acc[mi][j], ah[mi], bl);
                    mma16816(acc[mi][j], al[mi], bh);
                }
            }
        }
        __syncthreads();
    }
    float* dst = (wn == 0) ? g_P : g_Q;
#pragma unroll
    for (int mi = 0; mi < 2; mi++) {
#pragma unroll
        for (int j = 0; j < 8; j++) {
            int r = row0 + m0 + mi * 16 + g;
            int c = 8 * j + 2 * t;
            if (r < NN)
                *reinterpret_cast<float2*>(&dst[(size_t)r * 64 + c]) =
                    make_float2(acc[mi][j][0], acc[mi][j][1]);
            if (r + 8 < NN)
                *reinterpret_cast<float2*>(&dst[(size_t)(r + 8) * 64 + c]) =
                    make_float2(acc[mi][j][2], acc[mi][j][3]);
        }
    }
}

// ---------------- per-node aggregation (warp/node, sequential ea, bf16 epilogue) ----------------
__global__ void __launch_bounds__(256) k_agg() {
    int warp = (blockIdx.x * blockDim.x + threadIdx.x) >> 5;
    int lane = threadIdx.x & 31;
    if (warp >= NN) return;
    int n = warp;
    int fp = 2 * lane;
    u64 wc2[16];
#pragma unroll
    for (int k = 0; k < 16; k++) wc2[k] = *reinterpret_cast<const u64*>(&g_Wc[k * 64 + fp]);
    u64 base2 = fadd2(*reinterpret_cast<const u64*>(&g_P[(size_t)n * FF + fp]),
                      *reinterpret_cast<const u64*>(&g_hb[fp]));
    int s = g_rowptr[n], e = g_rowptr[n + 1];
    u64 sum2 = 0ull, sq2 = 0ull;
    float mn0 = 3.4e38f, mn1 = 3.4e38f, mx0 = -3.4e38f, mx1 = -3.4e38f;
    int src_n = 0; u64 q_n = 0ull;
    if (s < e) {
        src_n = g_csr_src[s];
        q_n = *reinterpret_cast<const u64*>(&g_Q[(size_t)src_n * FF + fp]);
    }
    for (int i = s; i < e; i++) {
        u64 qv = q_n;
        if (i + 1 < e) {
            src_n = g_csr_src[i + 1];
            q_n = *reinterpret_cast<const u64*>(&g_Q[(size_t)src_n * FF + fp]);
        }
        const float* ep = &g_eaperm[(size_t)i * EDD];   // sequential!
        float eav[16];
#pragma unroll
        for (int k = 0; k < 16; k += 4) {
            float4 v = *reinterpret_cast<const float4*>(ep + k);
            eav[k] = v.x; eav[k + 1] = v.y; eav[k + 2] = v.z; eav[k + 3] = v.w;
        }
        u64 hA = fadd2(base2, qv);
        u64 p0 = 0ull, p1 = 0ull;
#pragma unroll
        for (int k = 0; k < 8; k++) {
            p0 = ffma2(pk2(eav[2 * k], eav[2 * k]), wc2[2 * k], p0);
            p1 = ffma2(pk2(eav[2 * k + 1], eav[2 * k + 1]), wc2[2 * k + 1], p1);
        }
        u64 h2 = fadd2(hA, fadd2(p0, p1));
        sum2 = fadd2(sum2, h2);
        sq2 = ffma2(h2, h2, sq2);
        float2 h = up2(h2);
        mn0 = fminf(mn0, h.x); mx0 = fmaxf(mx0, h.x);
        mn1 = fminf(mn1, h.y); mx1 = fmaxf(mx1, h.y);
    }
    float deg = (float)(e - s);
    float degc = fmaxf(deg, 1.0f);
    float2 sum = up2(sum2), sq = up2(sq2);
    float mean0 = sum.x / degc, mean1 = sum.y / degc;
    float std0 = sqrtf(fmaxf(sq.x / degc - mean0 * mean0, 0.f) + 1e-5f);
    float std1 = sqrtf(fmaxf(sq.y / degc - mean1 * mean1, 0.f) + 1e-5f);
    if (deg == 0.f) { mn0 = 0.f; mx0 = 0.f; mn1 = 0.f; mx1 = 0.f; }
    __nv_bfloat16* ah = &g_Ah[(size_t)n * 320 + 64 + fp];
    __nv_bfloat16* al = &g_Al[(size_t)n * 320 + 64 + fp];
    u32 hi, lo;
    bfsplit2(mean0, mean1, hi, lo);
    *reinterpret_cast<u32*>(ah + 0)   = hi; *reinterpret_cast<u32*>(al + 0)   = lo;
    bfsplit2(mn0, mn1, hi, lo);
    *reinterpret_cast<u32*>(ah + 64)  = hi; *reinterpret_cast<u32*>(al + 64)  = lo;
    bfsplit2(mx0, mx1, hi, lo);
    *reinterpret_cast<u32*>(ah + 128) = hi; *reinterpret_cast<u32*>(al + 128) = lo;
    bfsplit2(std0, std1, hi, lo);
    *reinterpret_cast<u32*>(ah + 192) = hi; *reinterpret_cast<u32*>(al + 192) = lo;
}

// ---------------- main TC GEMM: C[N,192] = A @ B2, bf16 3-term split ----------------
__global__ void __launch_bounds__(256) k_gemm_tc() {
    __shared__ __nv_bfloat16 sAh[128 * PITCH];
    __shared__ __nv_bfloat16 sAl[128 * PITCH];
    __shared__ __nv_bfloat16 sBh[96 * PITCH];
    __shared__ __nv_bfloat16 sBl[96 * PITCH];
    int tid = threadIdx.x;
    int warp = tid >> 5, lane = tid & 31;
    int g = lane >> 2, t = lane & 3;
    int wm = warp >> 1, wn = warp & 1;
    int m0 = wm * 32;
    int nloc0 = wn * 48;
    int row0 = blockIdx.x * 128;
    int c0 = blockIdx.y * 96;
    float acc[2][6][4];
#pragma unroll
    for (int mi = 0; mi < 2; mi++)
#pragma unroll
        for (int j = 0; j < 6; j++)
#pragma unroll
            for (int q = 0; q < 4; q++) acc[mi][j][q] = 0.f;

    for (int kc = 0; kc < 320; kc += 32) {
#pragma unroll
        for (int it = 0; it < 4; it++) {
            int idx = tid + it * 256;
            int r = idx >> 3, kq = idx & 7;
            int n = row0 + r;
            u64 vh = 0ull, vl = 0ull;
            if (n < NN) {
                vh = *reinterpret_cast<const u64*>(&g_Ah[(size_t)n * 320 + kc + kq * 4]);
                vl = *reinterpret_cast<const u64*>(&g_Al[(size_t)n * 320 + kc + kq * 4]);
            }
            *reinterpret_cast<u64*>(&sAh[r * PITCH + kq * 4]) = vh;
            *reinterpret_cast<u64*>(&sAl[r * PITCH + kq * 4]) = vl;
        }
#pragma unroll
        for (int it = 0; it < 3; it++) {
            int idx = tid + it * 256;
            int r = idx >> 3, kq = idx & 7;
            *reinterpret_cast<u64*>(&sBh[r * PITCH + kq * 4]) =
                *reinterpret_cast<const u64*>(&g_Bth[(size_t)(c0 + r) * 320 + kc + kq * 4]);
            *reinterpret_cast<u64*>(&sBl[r * PITCH + kq * 4]) =
                *reinterpret_cast<const u64*>(&g_Btl[(size_t)(c0 + r) * 320 + kc + kq * 4]);
        }
        __syncthreads();
#pragma unroll
        for (int kk = 0; kk < 32; kk += 16) {
            u32 ah[2][4], al[2][4];
#pragma unroll
            for (int mi = 0; mi < 2; mi++) {
                int r = m0 + mi * 16 + g;
                int cA = kk + 2 * t;
                ah[mi][0] = *reinterpret_cast<const u32*>(&sAh[r * PITCH + cA]);
                ah[mi][1] = *reinterpret_cast<const u32*>(&sAh[(r + 8) * PITCH + cA]);
                ah[mi][2] = *reinterpret_cast<const u32*>(&sAh[r * PITCH + cA + 8]);
                ah[mi][3] = *reinterpret_cast<const u32*>(&sAh[(r + 8) * PITCH + cA + 8]);
                al[mi][0] = *reinterpret_cast<const u32*>(&sAl[r * PITCH + cA]);
                al[mi][1] = *reinterpret_cast<const u32*>(&sAl[(r + 8) * PITCH + cA]);
                al[mi][2] = *reinterpret_cast<const u32*>(&sAl[r * PITCH + cA + 8]);
                al[mi][3] = *reinterpret_cast<const u32*>(&sAl[(r + 8) * PITCH + cA + 8]);
            }
#pragma unroll
            for (int j = 0; j < 6; j++) {
                int nr = nloc0 + 8 * j + g;
                int cB = kk + 2 * t;
                u32 bh[2], bl[2];
                bh[0] = *reinterpret_cast<const u32*>(&sBh[nr * PITCH + cB]);
                bh[1] = *reinterpret_cast<const u32*>(&sBh[nr * PITCH + cB + 8]);
                bl[0] = *reinterpret_cast<const u32*>(&sBl[nr * PITCH + cB]);
                bl[1] = *reinterpret_cast<const u32*>(&sBl[nr * PITCH + cB + 8]);
#pragma unroll
                for (int mi = 0; mi < 2; mi++) {
                    mma16816(acc[mi][j], ah[mi], bh);
                    mma16816(acc[mi][j], ah[mi], bl);
                    mma16816(acc[mi][j], al[mi], bh);
                }
            }
        }
        __syncthreads();
    }
#pragma unroll
    for (int mi = 0; mi < 2; mi++) {
#pragma unroll
        for (int j = 0; j < 6; j++) {
            int r = row0 + m0 + mi * 16 + g;
            int c = c0 + nloc0 + 8 * j + 2 * t;
            if (r < NN)
                *reinterpret_cast<float2*>(&g_C[(size_t)r * 192 + c]) =
                    make_float2(acc[mi][j][0], acc[mi][j][1]);
            if (r + 8 < NN)
                *reinterpret_cast<float2*>(&g_C[(size_t)(r + 8) * 192 + c]) =
                    make_float2(acc[mi][j][2], acc[mi][j][3]);
        }
    }
}

// ---------------- elementwise combine (Wlin pre-folded) + BN stats ----------------
__global__ void __launch_bounds__(256) k_post() {
    int f = threadIdx.x & 63;
    int g = threadIdx.x >> 6;
    __shared__ float sred[256];
    float b2v = g_bias2[f];
    float ys = 0.f, yq = 0.f;
    int n0 = blockIdx.x * 64;
    for (int it = 0; it < 16; it++) {
        int n = n0 + it * 4 + g;
        if (n < NN) {
            const float* c = &g_C[(size_t)n * 192];
            float y = c[f] + g_amp[n] * c[64 + f] + g_att[n] * c[128 + f] + b2v;
            g_y[(size_t)n * FF + f] = y;
            ys += y;
            yq = fmaf(y, y, yq);
        }
    }
    sred[threadIdx.x] = ys;
    __syncthreads();
    if (threadIdx.x < 64) {
        float s = sred[f] + sred[64 + f] + sred[128 + f] + sred[192 + f];
        atomicAdd(&g_bnsum[f], s);
    }
    __syncthreads();
    sred[threadIdx.x] = yq;
    __syncthreads();
    if (threadIdx.x < 64) {
        float s = sred[f] + sred[64 + f] + sred[128 + f] + sred[192 + f];
        atomicAdd(&g_bnsq[f], s);
    }
}

__global__ void k_bnfin(const float* __restrict__ gamma_l, const float* __restrict__ beta_l) {
    int f = threadIdx.x;
    if (f >= FF) return;
    float mu = g_bnsum[f] / (float)NN;
    float var = g_bnsq[f] / (float)NN - mu * mu;
    float rs = rsqrtf(var + 1e-5f);
    float a = rs * gamma_l[f];
    g_bnA[f] = a;
    g_bnB[f] = beta_l[f] - mu * a;
}

// layer-0: BN + ReLU -> A cols 0..63 (bf16 split) only
__global__ void k_bnapply() {
    int gid = blockIdx.x * blockDim.x + threadIdx.x;
    if (gid >= NN * 16) return;
    int r = gid >> 4, q = gid & 15;
    int f0 = q * 4;
    float4 y = *reinterpret_cast<const float4*>(&g_y[(size_t)r * 64 + f0]);
    float v0 = fmaxf(y.x * g_bnA[f0 + 0] + g_bnB[f0 + 0], 0.f);
    float v1 = fmaxf(y.y * g_bnA[f0 + 1] + g_bnB[f0 + 1], 0.f);
    float v2 = fmaxf(y.z * g_bnA[f0 + 2] + g_bnB[f0 + 2], 0.f);
    float v3 = fmaxf(y.w * g_bnA[f0 + 3] + g_bnB[f0 + 3], 0.f);
    u32 h0, l0, h1, l1;
    bfsplit2(v0, v1, h0, l0);
    bfsplit2(v2, v3, h1, l1);
    *reinterpret_cast<u64*>(&g_Ah[(size_t)r * 320 + f0]) = (u64)h0 | ((u64)h1 << 32);
    *reinterpret_cast<u64*>(&g_Al[(size_t)r * 320 + f0]) = (u64)l0 | ((u64)l1 << 32);
}

// layer-1: BN + ReLU + mean-pool accumulate
__global__ void k_bnpool(const int* __restrict__ batch) {
    int gid = blockIdx.x * blockDim.x + threadIdx.x;
    if (gid >= NN * FF) return;
    int n = gid >> 6, f = gid & 63;
    float v = fmaxf(g_y[gid] * g_bnA[f] + g_bnB[f], 0.f);
    int b = batch[n];
    atomicAdd(&g_gsum[b * FF + f], v);
    if (f == 0) atomicAdd(&g_gcnt[b], 1);
}

__global__ void k_head(const float* __restrict__ W1, const float* __restrict__ b1,
                       const float* __restrict__ W2, const float* __restrict__ b2,
                       float* __restrict__ out) {
    int g = threadIdx.x;
    if (g >= GG) return;
    float cnt = fmaxf((float)g_gcnt[g], 1.0f);
    float inv = 1.0f / cnt;
    float gm[64];
#pragma unroll
    for (int k = 0; k < 64; k++) gm[k] = g_gsum[g * FF + k] * inv;
    float o = b2[0];
    for (int j = 0; j < 40; j++) {
        float s = b1[j];
#pragma unroll
        for (int k = 0; k < 64; k++) s = fmaf(gm[k], W1[k * 40 + j], s);
        o = fmaf(fmaxf(s, 0.f), W2[j], o);
    }
    out[g] = o;
}

// ---------------- launch ----------------
extern "C" void kernel_launch(void* const* d_in, const int* in_sizes, int n_in,
                              void* d_out, int out_size) {
    const float* x     = (const float*)d_in[0];
    const float* ea    = (const float*)d_in[1];
    const float* We    = (const float*)d_in[2];
    const float* be    = (const float*)d_in[3];
    const float* Wpre  = (const float*)d_in[4];
    const float* bpre  = (const float*)d_in[5];
    const float* Wpost = (const float*)d_in[6];
    const float* bpost = (const float*)d_in[7];
    const float* Wlin  = (const float*)d_in[8];
    const float* blin  = (const float*)d_in[9];
    const float* gamma = (const float*)d_in[10];
    const float* beta  = (const float*)d_in[11];
    const float* W1    = (const float*)d_in[12];
    const float* b1    = (const float*)d_in[13];
    const float* W2    = (const float*)d_in[14];
    const float* b2    = (const float*)d_in[15];
    const int*   ei    = (const int*)d_in[16];
    const int*   batch = (const int*)d_in[17];
    float* out = (float*)d_out;

    k_init<<<256, 256>>>();                              // idx 0
    k_cvtX<<<(NN * 16 + 255) / 256, 256>>>(x);           // idx 1
    k_cvtW<<<(128 * 64 + 255) / 256, 256>>>(Wpre);       // idx 2
    k_pq_tc<<<(NN + 127) / 128, 256>>>();                // idx 3  <- PROFILED (layer-0 PQ)
    k_deg<<<(EE + 255) / 256, 256>>>(ei);                // idx 4
    k_scan1<<<SCB, 1024>>>();                            // idx 5
    k_scan3<<<SCB, 1024>>>();                            // idx 6
    k_scatter<<<(EE + 255) / 256, 256>>>(ei, ea);        // idx 7

    for (int l = 0; l < LL; l++) {
        k_prep<<<1, 256>>>(We + l * EDD * FF, be + l * FF, Wpre + l * 192 * FF, bpre + l * FF);
        k_pack<<<(320 * 192 + 255) / 256, 256>>>(Wpost + l * 832 * FF);
        k_pack2<<<(320 * 192 + 255) / 256, 256>>>(Wlin + l * FF * FF);
        k_bias2<<<1, 64>>>(bpost + l * FF, blin + l * FF, Wlin + l * FF * FF);
        k_cvtB<<<(320 * 192 + 255) / 256, 256>>>();
        if (l > 0) {
            k_cvtW<<<(128 * 64 + 255) / 256, 256>>>(Wpre + l * 192 * FF);
            k_pq_tc<<<(NN + 127) / 128, 256>>>();
        }
        k_agg<<<(NN + 7) / 8, 256>>>();
        dim3 gg((NN + 127) / 128, 2);
        k_gemm_tc<<<gg, 256>>>();
        k_post<<<(NN + 63) / 64, 256>>>();
        k_bnfin<<<1, 64>>>(gamma + l * FF, beta + l * FF);
        if (l == 0) k_bnapply<<<(NN * 16 + 255) / 256, 256>>>();
        else        k_bnpool<<<(NN * FF + 255) / 256, 256>>>(batch);
    }

    k_head<<<1, 64>>>(W1, b1, W2, b2, out);
}

// round 12
// speedup vs baseline: 1.5047x; 1.0459x over previous
#include <cuda_runtime.h>
#include <cuda_bf16.h>
#include <math.h>
#include <stddef.h>

#define NN 50000
#define EE 800000
#define FF 64
#define EDD 16
#define GG 64
#define LL 2
#define SCB ((NN + 1023) / 1024)

typedef unsigned long long u64;
typedef unsigned int u32;

// ---------------- packed f32x2 helpers ----------------
__device__ __forceinline__ u64 pk2(float x, float y) {
    u64 r; asm("mov.b64 %0,{%1,%2};" : "=l"(r) : "f"(x), "f"(y)); return r;
}
__device__ __forceinline__ float2 up2(u64 v) {
    float2 r; asm("mov.b64 {%0,%1},%2;" : "=f"(r.x), "=f"(r.y) : "l"(v)); return r;
}
__device__ __forceinline__ u64 ffma2(u64 a, u64 b, u64 c) {
    u64 d; asm("fma.rn.f32x2 %0,%1,%2,%3;" : "=l"(d) : "l"(a), "l"(b), "l"(c)); return d;
}
__device__ __forceinline__ u64 fadd2(u64 a, u64 b) {
    u64 d; asm("add.rn.f32x2 %0,%1,%2;" : "=l"(d) : "l"(a), "l"(b)); return d;
}

// ---------------- bf16 / mma / cp.async helpers ----------------
__device__ __forceinline__ void mma16816(float* d, const u32* a, const u32* b) {
    asm volatile("mma.sync.aligned.m16n8k16.row.col.f32.bf16.bf16.f32 "
                 "{%0,%1,%2,%3},{%4,%5,%6,%7},{%8,%9},{%0,%1,%2,%3};"
                 : "+f"(d[0]), "+f"(d[1]), "+f"(d[2]), "+f"(d[3])
                 : "r"(a[0]), "r"(a[1]), "r"(a[2]), "r"(a[3]), "r"(b[0]), "r"(b[1]));
}
__device__ __forceinline__ void bfsplit2(float a, float b, u32& hi, u32& lo) {
    __nv_bfloat16 ah = __float2bfloat16_rn(a);
    __nv_bfloat16 bh = __float2bfloat16_rn(b);
    __nv_bfloat16 al = __float2bfloat16_rn(a - __bfloat162float(ah));
    __nv_bfloat16 bl = __float2bfloat16_rn(b - __bfloat162float(bh));
    unsigned short ahs = *reinterpret_cast<unsigned short*>(&ah);
    unsigned short bhs = *reinterpret_cast<unsigned short*>(&bh);
    unsigned short als = *reinterpret_cast<unsigned short*>(&al);
    unsigned short bls = *reinterpret_cast<unsigned short*>(&bl);
    hi = (u32)ahs | ((u32)bhs << 16);
    lo = (u32)als | ((u32)bls << 16);
}
__device__ __forceinline__ u32 s2u(const void* p) {
    return (u32)__cvta_generic_to_shared(p);
}
__device__ __forceinline__ void cpa16(u32 dst, const void* src, int sz) {
    asm volatile("cp.async.cg.shared.global [%0],[%1],16,%2;" :: "r"(dst), "l"(src), "r"(sz));
}
#define CP_COMMIT asm volatile("cp.async.commit_group;")
#define CP_WAIT1  asm volatile("cp.async.wait_group 1;")
#define CP_WAIT0  asm volatile("cp.async.wait_group 0;")

// ---------------- scratch ----------------
__device__ int   g_deg[NN];
__device__ int   g_rowptr[NN + 1];
__device__ int   g_cursor[NN];
__device__ int   g_bsum[64];
__device__ int   g_csr_src[EE];
__device__ float g_eaperm[(size_t)EE * EDD];
__device__ float g_amp[NN];
__device__ float g_att[NN];
__device__ float g_logsum;
__device__ float g_P[NN * FF];
__device__ float g_Q[NN * FF];
__device__ float g_Wc[EDD * FF];
__device__ float g_hb[FF];
__device__ float g_Bp[320 * 192];
__device__ float g_Bp2[320 * 192];
__device__ float g_bias2[FF];
__device__ float g_C[(size_t)NN * 192];
__device__ float g_y[NN * FF];
__device__ float g_bnsum[FF];
__device__ float g_bnsq[FF];
__device__ float g_bnA[FF];
__device__ float g_bnB[FF];
__device__ float g_gsum[GG * FF];
__device__ int   g_gcnt[GG];
__device__ __nv_bfloat16 g_Ah[(size_t)NN * 320];
__device__ __nv_bfloat16 g_Al[(size_t)NN * 320];
__device__ __nv_bfloat16 g_Bth[192 * 320];
__device__ __nv_bfloat16 g_Btl[192 * 320];
__device__ __nv_bfloat16 g_Wth[128 * 64];
__device__ __nv_bfloat16 g_Wtl[128 * 64];

// ---------------- init / degree / CSR ----------------
__global__ void k_init() {
    int i  = blockIdx.x * blockDim.x + threadIdx.x;
    int nt = gridDim.x * blockDim.x;
    for (int j = i; j < NN; j += nt) { g_deg[j] = 0; g_cursor[j] = 0; }
    for (int j = i; j < GG * FF; j += nt) g_gsum[j] = 0.f;
    if (i < GG) g_gcnt[i] = 0;
    if (i == 0) g_logsum = 0.f;
}

__global__ void k_deg(const int* __restrict__ ei) {
    int e = blockIdx.x * blockDim.x + threadIdx.x;
    if (e < EE) atomicAdd(&g_deg[ei[EE + e]], 1);
}

__global__ void k_scan1() {
    int tid = threadIdx.x, lane = tid & 31, wid = tid >> 5;
    int i = blockIdx.x * 1024 + tid;
    int v = (i < NN) ? g_deg[i] : 0;
    float lv = (i < NN) ? logf((float)v + 1.0f) : 0.0f;
#pragma unroll
    for (int off = 16; off > 0; off >>= 1) lv += __shfl_xor_sync(0xffffffffu, lv, off);
    if (lane == 0) atomicAdd(&g_logsum, lv);
    int x = v;
#pragma unroll
    for (int off = 1; off < 32; off <<= 1) {
        int t = __shfl_up_sync(0xffffffffu, x, off);
        if (lane >= off) x += t;
    }
    __shared__ int ws[32];
    if (lane == 31) ws[wid] = x;
    __syncthreads();
    if (wid == 0) {
        int s = ws[lane];
#pragma unroll
        for (int off = 1; off < 32; off <<= 1) {
            int t = __shfl_up_sync(0xffffffffu, s, off);
            if (lane >= off) s += t;
        }
        ws[lane] = s;
    }
    __syncthreads();
    int wbase = wid ? ws[wid - 1] : 0;
    if (i < NN) g_rowptr[i] = wbase + x - v;
    if (tid == 1023) g_bsum[blockIdx.x] = wbase + x;
}

__global__ void k_scan3() {
    __shared__ int sb[64];
    __shared__ int s_off, s_tot;
    int t = threadIdx.x;
    if (t < 64) sb[t] = (t < SCB) ? g_bsum[t] : 0;
    __syncthreads();
    if (t == 0) {
        int off = 0, tot = 0;
        for (int j = 0; j < SCB; j++) {
            if (j < (int)blockIdx.x) off += sb[j];
            tot += sb[j];
        }
        s_off = off; s_tot = tot;
    }
    __syncthreads();
    int i = blockIdx.x * 1024 + t;
    if (i < NN) {
        g_rowptr[i] += s_off;
        float avg = g_logsum / (float)NN;
        float d = (float)g_deg[i];
        float logd = logf(fmaxf(d, 1.0f) + 1.0f);
        g_amp[i] = logd / avg;
        g_att[i] = avg / logd;
    }
    if (blockIdx.x == gridDim.x - 1 && t == 0) g_rowptr[NN] = s_tot;
}

__global__ void k_scatter(const int* __restrict__ ei, const float* __restrict__ eattr) {
    int e = blockIdx.x * blockDim.x + threadIdx.x;
    if (e >= EE) return;
    int d = ei[EE + e];
    int pos = g_rowptr[d] + atomicAdd(&g_cursor[d], 1);
    g_csr_src[pos] = ei[e];
    const float4* srcp = reinterpret_cast<const float4*>(&eattr[(size_t)e * EDD]);
    float4* dstp = reinterpret_cast<float4*>(&g_eaperm[(size_t)pos * EDD]);
    dstp[0] = srcp[0];
    dstp[1] = srcp[1];
    dstp[2] = srcp[2];
    dstp[3] = srcp[3];
}

// ---------------- per-layer small prep ----------------
__global__ void k_prep(const float* __restrict__ We_l, const float* __restrict__ be_l,
                       const float* __restrict__ Wpre_l, const float* __restrict__ bpre_l) {
    int tid = threadIdx.x;
    if (tid < FF) { g_bnsum[tid] = 0.f; g_bnsq[tid] = 0.f; }
    for (int idx = tid; idx < EDD * FF; idx += 256) {
        int j = idx / FF, f = idx % FF;
        float s = 0.f;
        for (int m = 0; m < FF; m++)
            s += We_l[j * FF + m] * Wpre_l[(128 + m) * FF + f];
        g_Wc[idx] = s;
    }
    if (tid < FF) {
        float s = bpre_l[tid];
        for (int m = 0; m < FF; m++)
            s += be_l[m] * Wpre_l[(128 + m) * FF + tid];
        g_hb[tid] = s;
    }
}

__global__ void k_pack(const float* __restrict__ Wpost_l) {
    int idx = blockIdx.x * blockDim.x + threadIdx.x;
    if (idx >= 320 * 192) return;
    int r = idx / 192, c = idx % 192;
    float v;
    if (r < 64) {
        v = (c < 64) ? Wpost_l[r * 64 + c] : 0.f;
    } else {
        int k = r - 64;
        int blk = c >> 6, cc = c & 63;
        v = Wpost_l[(64 + blk * 256 + k) * 64 + cc];
    }
    g_Bp[idx] = v;
}

__global__ void k_pack2(const float* __restrict__ Wlin_l) {
    int idx = blockIdx.x * blockDim.x + threadIdx.x;
    if (idx >= 320 * 192) return;
    int r = idx / 192, c = idx % 192;
    int blk = c >> 6, cc = c & 63;
    const float* bsrc = &g_Bp[r * 192 + blk * 64];
    float s = 0.f;
#pragma unroll 8
    for (int m = 0; m < 64; m++)
        s += bsrc[m] * __ldg(&Wlin_l[m * 64 + cc]);
    g_Bp2[idx] = s;
}

__global__ void k_bias2(const float* __restrict__ bpost_l, const float* __restrict__ blin_l,
                        const float* __restrict__ Wlin_l) {
    int cc = threadIdx.x;
    if (cc >= FF) return;
    float s = blin_l[cc];
    for (int m = 0; m < 64; m++)
        s += bpost_l[m] * Wlin_l[m * 64 + cc];
    g_bias2[cc] = s;
}

__global__ void k_cvtB() {
    int idx = blockIdx.x * blockDim.x + threadIdx.x;
    if (idx >= 320 * 192) return;
    int k = idx / 192, c = idx % 192;
    float v = g_Bp2[idx];
    __nv_bfloat16 h = __float2bfloat16_rn(v);
    __nv_bfloat16 l = __float2bfloat16_rn(v - __bfloat162float(h));
    g_Bth[c * 320 + k] = h;
    g_Btl[c * 320 + k] = l;
}

__global__ void k_cvtW(const float* __restrict__ Wpre_l) {
    int idx = blockIdx.x * blockDim.x + threadIdx.x;
    if (idx >= 128 * 64) return;
    int c = idx >> 6, k = idx & 63;
    float v = (c < 64) ? Wpre_l[k * 64 + c] : Wpre_l[(64 + k) * 64 + (c - 64)];
    __nv_bfloat16 h = __float2bfloat16_rn(v);
    __nv_bfloat16 l = __float2bfloat16_rn(v - __bfloat162float(h));
    g_Wth[c * 64 + k] = h;
    g_Wtl[c * 64 + k] = l;
}

__global__ void k_cvtX(const float* __restrict__ X) {
    int gid = blockIdx.x * blockDim.x + threadIdx.x;
    if (gid >= NN * 16) return;
    int r = gid >> 4, q = gid & 15;
    float4 v = *reinterpret_cast<const float4*>(&X[(size_t)r * 64 + q * 4]);
    u32 h0, l0, h1, l1;
    bfsplit2(v.x, v.y, h0, l0);
    bfsplit2(v.z, v.w, h1, l1);
    *reinterpret_cast<u64*>(&g_Ah[(size_t)r * 320 + q * 4]) = (u64)h0 | ((u64)h1 << 32);
    *reinterpret_cast<u64*>(&g_Al[(size_t)r * 320 + q * 4]) = (u64)l0 | ((u64)l1 << 32);
}

// ================= pipelined TC GEMM skeleton: 64x64 tile, 128 thr =================
#define PITCH 40

// stage loaders: 64 rows x 32 k (one chunk) per buffer; 2 iters x 128 thr = 256 cp.async per buf
__device__ __forceinline__ void stageA(__nv_bfloat16* sAh, __nv_bfloat16* sAl,
                                       int row0, int kc, int tid) {
#pragma unroll
    for (int it = 0; it < 2; it++) {
        int idx = tid + it * 128;         // 0..255
        int r = idx >> 2, q = idx & 3;    // 64 rows, 4 x 16B
        int n = row0 + r;
        int nc = (n < NN) ? n : (NN - 1);
        int sz = (n < NN) ? 16 : 0;
        cpa16(s2u(sAh + r * PITCH + q * 8), &g_Ah[(size_t)nc * 320 + kc + q * 8], sz);
        cpa16(s2u(sAl + r * PITCH + q * 8), &g_Al[(size_t)nc * 320 + kc + q * 8], sz);
    }
}
__device__ __forceinline__ void stageB(__nv_bfloat16* sBh, __nv_bfloat16* sBl,
                                       const __nv_bfloat16* Bh, const __nv_bfloat16* Bl,
                                       int bstride, int c0, int kc, int tid) {
#pragma unroll
    for (int it = 0; it < 2; it++) {
        int idx = tid + it * 128;
        int r = idx >> 2, q = idx & 3;
        cpa16(s2u(sBh + r * PITCH + q * 8), &Bh[(size_t)(c0 + r) * bstride + kc + q * 8], 16);
        cpa16(s2u(sBl + r * PITCH + q * 8), &Bl[(size_t)(c0 + r) * bstride + kc + q * 8], 16);
    }
}

// compute one 32-k chunk: 4 warps, warp = (wm rows 32, wn cols 32), acc[2][4][4]
__device__ __forceinline__ void tcchunk(const __nv_bfloat16* sAh, const __nv_bfloat16* sAl,
                                        const __nv_bfloat16* sBh, const __nv_bfloat16* sBl,
                                        int m0, int n0l, int g, int t, float acc[2][4][4]) {
#pragma unroll
    for (int kk = 0; kk < 32; kk += 16) {
        u32 ah[2][4], al[2][4];
#pragma unroll
        for (int mi = 0; mi < 2; mi++) {
            int r = m0 + mi * 16 + g;
            int cA = kk + 2 * t;
            ah[mi][0] = *reinterpret_cast<const u32*>(&sAh[r * PITCH + cA]);
            ah[mi][1] = *reinterpret_cast<const u32*>(&sAh[(r + 8) * PITCH + cA]);
            ah[mi][2] = *reinterpret_cast<const u32*>(&sAh[r * PITCH + cA + 8]);
            ah[mi][3] = *reinterpret_cast<const u32*>(&sAh[(r + 8) * PITCH + cA + 8]);
            al[mi][0] = *reinterpret_cast<const u32*>(&sAl[r * PITCH + cA]);
            al[mi][1] = *reinterpret_cast<const u32*>(&sAl[(r + 8) * PITCH + cA]);
            al[mi][2] = *reinterpret_cast<const u32*>(&sAl[r * PITCH + cA + 8]);
            al[mi][3] = *reinterpret_cast<const u32*>(&sAl[(r + 8) * PITCH + cA + 8]);
        }
#pragma unroll
        for (int j = 0; j < 4; j++) {
            int nr = n0l + 8 * j + g;
            int cB = kk + 2 * t;
            u32 bh[2], bl[2];
            bh[0] = *reinterpret_cast<const u32*>(&sBh[nr * PITCH + cB]);
            bh[1] = *reinterpret_cast<const u32*>(&sBh[nr * PITCH + cB + 8]);
            bl[0] = *reinterpret_cast<const u32*>(&sBl[nr * PITCH + cB]);
            bl[1] = *reinterpret_cast<const u32*>(&sBl[nr * PITCH + cB + 8]);
#pragma unroll
            for (int mi = 0; mi < 2; mi++) {
                mma16816(acc[mi][j], ah[mi], bh);
                mma16816(acc[mi][j], ah[mi], bl);
                mma16816(acc[mi][j], al[mi], bh);
            }
        }
    }
}

// ---- main GEMM: C[N,192] = A @ B2 ; grid (782, 3), 128 thr ----
__global__ void __launch_bounds__(128) k_gemm_tc() {
    __shared__ __nv_bfloat16 sAh[2][64 * PITCH];
    __shared__ __nv_bfloat16 sAl[2][64 * PITCH];
    __shared__ __nv_bfloat16 sBh[2][64 * PITCH];
    __shared__ __nv_bfloat16 sBl[2][64 * PITCH];
    int tid = threadIdx.x;
    int warp = tid >> 5, lane = tid & 31;
    int g = lane >> 2, t = lane & 3;
    int wm = warp >> 1, wn = warp & 1;
    int m0 = wm * 32, n0l = wn * 32;
    int row0 = blockIdx.x * 64;
    int c0 = blockIdx.y * 64;
    float acc[2][4][4];
#pragma unroll
    for (int mi = 0; mi < 2; mi++)
#pragma unroll
        for (int j = 0; j < 4; j++)
#pragma unroll
            for (int q = 0; q < 4; q++) acc[mi][j][q] = 0.f;

    stageA(sAh[0], sAl[0], row0, 0, tid);
    stageB(sBh[0], sBl[0], g_Bth, g_Btl, 320, c0, 0, tid);
    CP_COMMIT;
    for (int i = 0; i < 10; i++) {
        int s = i & 1;
        if (i + 1 < 10) {
            stageA(sAh[s ^ 1], sAl[s ^ 1], row0, (i + 1) * 32, tid);
            stageB(sBh[s ^ 1], sBl[s ^ 1], g_Bth, g_Btl, 320, c0, (i + 1) * 32, tid);
            CP_COMMIT;
            CP_WAIT1;
        } else {
            CP_WAIT0;
        }
        __syncthreads();
        tcchunk(sAh[s], sAl[s], sBh[s], sBl[s], m0, n0l, g, t, acc);
        __syncthreads();
    }
#pragma unroll
    for (int mi = 0; mi < 2; mi++) {
#pragma unroll
        for (int j = 0; j < 4; j++) {
            int r = row0 + m0 + mi * 16 + g;
            int c = c0 + n0l + 8 * j + 2 * t;
            if (r < NN)
                *reinterpret_cast<float2*>(&g_C[(size_t)r * 192 + c]) =
                    make_float2(acc[mi][j][0], acc[mi][j][1]);
            if (r + 8 < NN)
                *reinterpret_cast<float2*>(&g_C[(size_t)(r + 8) * 192 + c]) =
                    make_float2(acc[mi][j][2], acc[mi][j][3]);
        }
    }
}

// ---- PQ GEMM: [P|Q][N,128] = X @ Wt ; grid (782, 2), 128 thr ----
__global__ void __launch_bounds__(128) k_pq_tc() {
    __shared__ __nv_bfloat16 sAh[2][64 * PITCH];
    __shared__ __nv_bfloat16 sAl[2][64 * PITCH];
    __shared__ __nv_bfloat16 sBh[2][64 * PITCH];
    __shared__ __nv_bfloat16 sBl[2][64 * PITCH];
    int tid = threadIdx.x;
    int warp = tid >> 5, lane = tid & 31;
    int g = lane >> 2, t = lane & 3;
    int wm = warp >> 1, wn = warp & 1;
    int m0 = wm * 32, n0l = wn * 32;
    int row0 = blockIdx.x * 64;
    int cb = blockIdx.y * 64;   // 0 -> P, 64 -> Q
    float acc[2][4][4];
#pragma unroll
    for (int mi = 0; mi < 2; mi++)
#pragma unroll
        for (int j = 0; j < 4; j++)
#pragma unroll
            for (int q = 0; q < 4; q++) acc[mi][j][q] = 0.f;

    stageA(sAh[0], sAl[0], row0, 0, tid);
    stageB(sBh[0], sBl[0], g_Wth, g_Wtl, 64, cb, 0, tid);
    CP_COMMIT;
#pragma unroll
    for (int i = 0; i < 2; i++) {
        int s = i & 1;
        if (i + 1 < 2) {
            stageA(sAh[s ^ 1], sAl[s ^ 1], row0, 32, tid);
            stageB(sBh[s ^ 1], sBl[s ^ 1], g_Wth, g_Wtl, 64, cb, 32, tid);
            CP_COMMIT;
            CP_WAIT1;
        } else {
            CP_WAIT0;
        }
        __syncthreads();
        tcchunk(sAh[s], sAl[s], sBh[s], sBl[s], m0, n0l, g, t, acc);
        __syncthreads();
    }
    float* dst = (cb == 0) ? g_P : g_Q;
#pragma unroll
    for (int mi = 0; mi < 2; mi++) {
#pragma unroll
        for (int j = 0; j < 4; j++) {
            int r = row0 + m0 + mi * 16 + g;
            int c = n0l + 8 * j + 2 * t;
            if (r < NN)
                *reinterpret_cast<float2*>(&dst[(size_t)r * 64 + c]) =
                    make_float2(acc[mi][j][0], acc[mi][j][1]);
            if (r + 8 < NN)
                *reinterpret_cast<float2*>(&dst[(size_t)(r + 8) * 64 + c]) =
                    make_float2(acc[mi][j][2], acc[mi][j][3]);
        }
    }
}

// ---------------- per-node aggregation ----------------
__global__ void __launch_bounds__(256) k_agg() {
    int warp = (blockIdx.x * blockDim.x + threadIdx.x) >> 5;
    int lane = threadIdx.x & 31;
    if (warp >= NN) return;
    int n = warp;
    int fp = 2 * lane;
    u64 wc2[16];
#pragma unroll
    for (int k = 0; k < 16; k++) wc2[k] = *reinterpret_cast<const u64*>(&g_Wc[k * 64 + fp]);
    u64 base2 = fadd2(*reinterpret_cast<const u64*>(&g_P[(size_t)n * FF + fp]),
                      *reinterpret_cast<const u64*>(&g_hb[fp]));
    int s = g_rowptr[n], e = g_rowptr[n + 1];
    u64 sum2 = 0ull, sq2 = 0ull;
    float mn0 = 3.4e38f, mn1 = 3.4e38f, mx0 = -3.4e38f, mx1 = -3.4e38f;
    int src_n = 0; u64 q_n = 0ull;
    if (s < e) {
        src_n = g_csr_src[s];
        q_n = *reinterpret_cast<const u64*>(&g_Q[(size_t)src_n * FF + fp]);
    }
    for (int i = s; i < e; i++) {
        u64 qv = q_n;
        if (i + 1 < e) {
            src_n = g_csr_src[i + 1];
            q_n = *reinterpret_cast<const u64*>(&g_Q[(size_t)src_n * FF + fp]);
        }
        const float* ep = &g_eaperm[(size_t)i * EDD];
        float eav[16];
#pragma unroll
        for (int k = 0; k < 16; k += 4) {
            float4 v = *reinterpret_cast<const float4*>(ep + k);
            eav[k] = v.x; eav[k + 1] = v.y; eav[k + 2] = v.z; eav[k + 3] = v.w;
        }
        u64 hA = fadd2(base2, qv);
        u64 p0 = 0ull, p1 = 0ull;
#pragma unroll
        for (int k = 0; k < 8; k++) {
            p0 = ffma2(pk2(eav[2 * k], eav[2 * k]), wc2[2 * k], p0);
            p1 = ffma2(pk2(eav[2 * k + 1], eav[2 * k + 1]), wc2[2 * k + 1], p1);
        }
        u64 h2 = fadd2(hA, fadd2(p0, p1));
        sum2 = fadd2(sum2, h2);
        sq2 = ffma2(h2, h2, sq2);
        float2 h = up2(h2);
        mn0 = fminf(mn0, h.x); mx0 = fmaxf(mx0, h.x);
        mn1 = fminf(mn1, h.y); mx1 = fmaxf(mx1, h.y);
    }
    float deg = (float)(e - s);
    float degc = fmaxf(deg, 1.0f);
    float2 sum = up2(sum2), sq = up2(sq2);
    float mean0 = sum.x / degc, mean1 = sum.y / degc;
    float std0 = sqrtf(fmaxf(sq.x / degc - mean0 * mean0, 0.f) + 1e-5f);
    float std1 = sqrtf(fmaxf(sq.y / degc - mean1 * mean1, 0.f) + 1e-5f);
    if (deg == 0.f) { mn0 = 0.f; mx0 = 0.f; mn1 = 0.f; mx1 = 0.f; }
    __nv_bfloat16* ah = &g_Ah[(size_t)n * 320 + 64 + fp];
    __nv_bfloat16* al = &g_Al[(size_t)n * 320 + 64 + fp];
    u32 hi, lo;
    bfsplit2(mean0, mean1, hi, lo);
    *reinterpret_cast<u32*>(ah + 0)   = hi; *reinterpret_cast<u32*>(al + 0)   = lo;
    bfsplit2(mn0, mn1, hi, lo);
    *reinterpret_cast<u32*>(ah + 64)  = hi; *reinterpret_cast<u32*>(al + 64)  = lo;
    bfsplit2(mx0, mx1, hi, lo);
    *reinterpret_cast<u32*>(ah + 128) = hi; *reinterpret_cast<u32*>(al + 128) = lo;
    bfsplit2(std0, std1, hi, lo);
    *reinterpret_cast<u32*>(ah + 192) = hi; *reinterpret_cast<u32*>(al + 192) = lo;
}

// ---------------- elementwise combine + BN stats ----------------
__global__ void __launch_bounds__(256) k_post() {
    int f = threadIdx.x & 63;
    int g = threadIdx.x >> 6;
    __shared__ float sred[256];
    float b2v = g_bias2[f];
    float ys = 0.f, yq = 0.f;
    int n0 = blockIdx.x * 64;
    for (int it = 0; it < 16; it++) {
        int n = n0 + it * 4 + g;
        if (n < NN) {
            const float* c = &g_C[(size_t)n * 192];
            float y = c[f] + g_amp[n] * c[64 + f] + g_att[n] * c[128 + f] + b2v;
            g_y[(size_t)n * FF + f] = y;
            ys += y;
            yq = fmaf(y, y, yq);
        }
    }
    sred[threadIdx.x] = ys;
    __syncthreads();
    if (threadIdx.x < 64) {
        float s = sred[f] + sred[64 + f] + sred[128 + f] + sred[192 + f];
        atomicAdd(&g_bnsum[f], s);
    }
    __syncthreads();
    sred[threadIdx.x] = yq;
    __syncthreads();
    if (threadIdx.x < 64) {
        float s = sred[f] + sred[64 + f] + sred[128 + f] + sred[192 + f];
        atomicAdd(&g_bnsq[f], s);
    }
}

__global__ void k_bnfin(const float* __restrict__ gamma_l, const float* __restrict__ beta_l) {
    int f = threadIdx.x;
    if (f >= FF) return;
    float mu = g_bnsum[f] / (float)NN;
    float var = g_bnsq[f] / (float)NN - mu * mu;
    float rs = rsqrtf(var + 1e-5f);
    float a = rs * gamma_l[f];
    g_bnA[f] = a;
    g_bnB[f] = beta_l[f] - mu * a;
}

__global__ void k_bnapply() {
    int gid = blockIdx.x * blockDim.x + threadIdx.x;
    if (gid >= NN * 16) return;
    int r = gid >> 4, q = gid & 15;
    int f0 = q * 4;
    float4 y = *reinterpret_cast<const float4*>(&g_y[(size_t)r * 64 + f0]);
    float v0 = fmaxf(y.x * g_bnA[f0 + 0] + g_bnB[f0 + 0], 0.f);
    float v1 = fmaxf(y.y * g_bnA[f0 + 1] + g_bnB[f0 + 1], 0.f);
    float v2 = fmaxf(y.z * g_bnA[f0 + 2] + g_bnB[f0 + 2], 0.f);
    float v3 = fmaxf(y.w * g_bnA[f0 + 3] + g_bnB[f0 + 3], 0.f);
    u32 h0, l0, h1, l1;
    bfsplit2(v0, v1, h0, l0);
    bfsplit2(v2, v3, h1, l1);
    *reinterpret_cast<u64*>(&g_Ah[(size_t)r * 320 + f0]) = (u64)h0 | ((u64)h1 << 32);
    *reinterpret_cast<u64*>(&g_Al[(size_t)r * 320 + f0]) = (u64)l0 | ((u64)l1 << 32);
}

__global__ void k_bnpool(const int* __restrict__ batch) {
    int gid = blockIdx.x * blockDim.x + threadIdx.x;
    if (gid >= NN * FF) return;
    int n = gid >> 6, f = gid & 63;
    float v = fmaxf(g_y[gid] * g_bnA[f] + g_bnB[f], 0.f);
    int b = batch[n];
    atomicAdd(&g_gsum[b * FF + f], v);
    if (f == 0) atomicAdd(&g_gcnt[b], 1);
}

__global__ void k_head(const float* __restrict__ W1, const float* __restrict__ b1,
                       const float* __restrict__ W2, const float* __restrict__ b2,
                       float* __restrict__ out) {
    int g = threadIdx.x;
    if (g >= GG) return;
    float cnt = fmaxf((float)g_gcnt[g], 1.0f);
    float inv = 1.0f / cnt;
    float gm[64];
#pragma unroll
    for (int k = 0; k < 64; k++) gm[k] = g_gsum[g * FF + k] * inv;
    float o = b2[0];
    for (int j = 0; j < 40; j++) {
        float s = b1[j];
#pragma unroll
        for (int k = 0; k < 64; k++) s = fmaf(gm[k], W1[k * 40 + j], s);
        o = fmaf(fmaxf(s, 0.f), W2[j], o);
    }
    out[g] = o;
}

// ---------------- launch ----------------
extern "C" void kernel_launch(void* const* d_in, const int* in_sizes, int n_in,
                              void* d_out, int out_size) {
    const float* x     = (const float*)d_in[0];
    const float* ea    = (const float*)d_in[1];
    const float* We    = (const float*)d_in[2];
    const float* be    = (const float*)d_in[3];
    const float* Wpre  = (const float*)d_in[4];
    const float* bpre  = (const float*)d_in[5];
    const float* Wpost = (const float*)d_in[6];
    const float* bpost = (const float*)d_in[7];
    const float* Wlin  = (const float*)d_in[8];
    const float* blin  = (const float*)d_in[9];
    const float* gamma = (const float*)d_in[10];
    const float* beta  = (const float*)d_in[11];
    const float* W1    = (const float*)d_in[12];
    const float* b1    = (const float*)d_in[13];
    const float* W2    = (const float*)d_in[14];
    const float* b2    = (const float*)d_in[15];
    const int*   ei    = (const int*)d_in[16];
    const int*   batch = (const int*)d_in[17];
    float* out = (float*)d_out;

    dim3 gpq((NN + 63) / 64, 2);
    dim3 ggm((NN + 63) / 64, 3);

    k_init<<<256, 256>>>();                              // idx 0
    k_cvtX<<<(NN * 16 + 255) / 256, 256>>>(x);           // idx 1
    k_cvtW<<<(128 * 64 + 255) / 256, 256>>>(Wpre);       // idx 2
    k_pq_tc<<<gpq, 128>>>();                             // idx 3  <- PROFILED
    k_deg<<<(EE + 255) / 256, 256>>>(ei);                // idx 4
    k_scan1<<<SCB, 1024>>>();                            // idx 5
    k_scan3<<<SCB, 1024>>>();                            // idx 6
    k_scatter<<<(EE + 255) / 256, 256>>>(ei, ea);        // idx 7

    for (int l = 0; l < LL; l++) {
        k_prep<<<1, 256>>>(We + l * EDD * FF, be + l * FF, Wpre + l * 192 * FF, bpre + l * FF);
        k_pack<<<(320 * 192 + 255) / 256, 256>>>(Wpost + l * 832 * FF);
        k_pack2<<<(320 * 192 + 255) / 256, 256>>>(Wlin + l * FF * FF);
        k_bias2<<<1, 64>>>(bpost + l * FF, blin + l * FF, Wlin + l * FF * FF);
        k_cvtB<<<(320 * 192 + 255) / 256, 256>>>();
        if (l > 0) {
            k_cvtW<<<(128 * 64 + 255) / 256, 256>>>(Wpre + l * 192 * FF);
            k_pq_tc<<<gpq, 128>>>();
        }
        k_agg<<<(NN + 7) / 8, 256>>>();
        k_gemm_tc<<<ggm, 128>>>();
        k_post<<<(NN + 63) / 64, 256>>>();
        k_bnfin<<<1, 64>>>(gamma + l * FF, beta + l * FF);
        if (l == 0) k_bnapply<<<(NN * 16 + 255) / 256, 256>>>();
        else        k_bnpool<<<(NN * FF + 255) / 256, 256>>>(batch);
    }

    k_head<<<1, 64>>>(W1, b1, W2, b2, out);
}